// round 2
// baseline (speedup 1.0000x reference)
#include <cuda_runtime.h>
#include <cstddef>

#define B_   2
#define S_   2048
#define E_   2048
#define H_   32
#define HKV_ 8
#define D_   64
#define G_   4

// Scratch (zero-init .bss, no allocation)
__device__ float g_Q[(size_t)B_ * S_ * E_];            // (B,S,H*D) after Q proj
__device__ float g_K[(size_t)B_ * S_ * HKV_ * D_];     // (B,S,HKV*D)
__device__ float g_V[(size_t)B_ * S_ * HKV_ * D_];
__device__ float g_attn[(size_t)B_ * S_ * E_];         // (B,S,H*D) attention out

// ---------------------------------------------------------------------------
// NT GEMM: C[M,N] = A[M,K] @ B[N,K]^T   (A, B row-major, inner dim contiguous)
// 128x128x16 tile, 256 threads, 8x8 microtile.
// ---------------------------------------------------------------------------
__global__ __launch_bounds__(256) void gemm_nt_kernel(
    const float* __restrict__ A, const float* __restrict__ Bm,
    float* __restrict__ C, int M, int N, int K)
{
    const int BM = 128, BN = 128, BK = 16;
    __shared__ float As[BK][BM + 4];
    __shared__ float Bs[BK][BN + 4];

    int tid = threadIdx.x;
    int ty = tid >> 4;        // 0..15
    int tx = tid & 15;        // 0..15
    int m0 = blockIdx.y * BM;
    int n0 = blockIdx.x * BN;

    float acc[8][8];
#pragma unroll
    for (int i = 0; i < 8; i++)
#pragma unroll
        for (int j = 0; j < 8; j++) acc[i][j] = 0.0f;

    const float* Ab = A  + (size_t)m0 * K;
    const float* Bb = Bm + (size_t)n0 * K;

    int lr = tid >> 2;              // 0..63 (row within tile, plus +64)
    int fo = (tid & 3) << 2;        // k offset: 0,4,8,12

    for (int k0 = 0; k0 < K; k0 += BK) {
#pragma unroll
        for (int rr = 0; rr < 2; rr++) {
            int row = lr + rr * 64;
            float4 a = *(const float4*)(Ab + (size_t)row * K + k0 + fo);
            As[fo + 0][row] = a.x; As[fo + 1][row] = a.y;
            As[fo + 2][row] = a.z; As[fo + 3][row] = a.w;
            float4 b = *(const float4*)(Bb + (size_t)row * K + k0 + fo);
            Bs[fo + 0][row] = b.x; Bs[fo + 1][row] = b.y;
            Bs[fo + 2][row] = b.z; Bs[fo + 3][row] = b.w;
        }
        __syncthreads();

#pragma unroll
        for (int kk = 0; kk < BK; kk++) {
            float4 a0 = *(const float4*)&As[kk][ty * 8];
            float4 a1 = *(const float4*)&As[kk][ty * 8 + 4];
            float4 b0 = *(const float4*)&Bs[kk][tx * 8];
            float4 b1 = *(const float4*)&Bs[kk][tx * 8 + 4];
            float av[8] = {a0.x, a0.y, a0.z, a0.w, a1.x, a1.y, a1.z, a1.w};
            float bv[8] = {b0.x, b0.y, b0.z, b0.w, b1.x, b1.y, b1.z, b1.w};
#pragma unroll
            for (int i = 0; i < 8; i++)
#pragma unroll
                for (int j = 0; j < 8; j++)
                    acc[i][j] = fmaf(av[i], bv[j], acc[i][j]);
        }
        __syncthreads();
    }

#pragma unroll
    for (int i = 0; i < 8; i++) {
        float* Crow = C + (size_t)(m0 + ty * 8 + i) * N + n0 + tx * 8;
        *(float4*)Crow       = make_float4(acc[i][0], acc[i][1], acc[i][2], acc[i][3]);
        *(float4*)(Crow + 4) = make_float4(acc[i][4], acc[i][5], acc[i][6], acc[i][7]);
    }
}

// ---------------------------------------------------------------------------
// RoPE (in place): buf is (B,S,nheads,D). One thread per rotation pair.
// out[d]    = t[d]*cos[d]    - t[d+32]*sin[d]        (d < 32)
// out[d+32] = t[d+32]*cos[d+32] + t[d]*sin[d+32]
// ---------------------------------------------------------------------------
__global__ void rope_kernel(float* __restrict__ buf,
                            const float* __restrict__ cosT,
                            const float* __restrict__ sinT, int nheads)
{
    int idx = blockIdx.x * blockDim.x + threadIdx.x;
    int total = B_ * S_ * nheads * (D_ / 2);
    if (idx >= total) return;
    int d = idx & 31;
    int h = (idx >> 5) % nheads;
    int m = idx / (32 * nheads);          // 0..B*S-1
    int s = m % S_;
    size_t base = (size_t)m * nheads * D_ + h * D_;
    float q0 = buf[base + d];
    float q1 = buf[base + d + 32];
    float c0 = cosT[s * D_ + d],      s0 = sinT[s * D_ + d];
    float c1 = cosT[s * D_ + d + 32], s1 = sinT[s * D_ + d + 32];
    buf[base + d]      = q0 * c0 - q1 * s0;
    buf[base + d + 32] = q1 * c1 + q0 * s1;
}

// ---------------------------------------------------------------------------
// Flash attention (non-causal), Br=Bc=64, D=64, fp32, online softmax.
// grid: (S/64, H, B), 256 threads (16x16), each thread 4x4 microtiles.
// ---------------------------------------------------------------------------
#define TS 64
#define TSTRIDE 68   // 64 + 4 pad, keeps float4 alignment, staggers banks

__global__ __launch_bounds__(256) void attn_kernel()
{
    extern __shared__ float sm[];
    float* Qs  = sm;                      // 64 x 68 (pre-scaled by 1/8)
    float* KPs = sm + TS * TSTRIDE;       // K tile, then reused for P tile
    float* Vs  = sm + 2 * TS * TSTRIDE;

    int tid = threadIdx.x;
    int ty = tid >> 4, tx = tid & 15;
    int qt = blockIdx.x, h = blockIdx.y, b = blockIdx.z;
    int kvh = h >> 2;                     // G = 4
    int s0 = qt * TS;

    const float* Qb = g_Q + ((size_t)b * S_ + s0) * E_ + h * D_;
    const float* Kb = g_K + (size_t)b * S_ * (HKV_ * D_) + kvh * D_;
    const float* Vb = g_V + (size_t)b * S_ * (HKV_ * D_) + kvh * D_;

    // Load Q tile, pre-scaled by 1/sqrt(D) = 0.125
    for (int i = tid; i < TS * 16; i += 256) {
        int r = i >> 4, f = (i & 15) << 2;
        float4 v = *(const float4*)(Qb + (size_t)r * E_ + f);
        v.x *= 0.125f; v.y *= 0.125f; v.z *= 0.125f; v.w *= 0.125f;
        *(float4*)&Qs[r * TSTRIDE + f] = v;
    }

    float mst[4], lst[4], o[4][4];
#pragma unroll
    for (int i = 0; i < 4; i++) {
        mst[i] = -1e30f; lst[i] = 0.0f;
#pragma unroll
        for (int j = 0; j < 4; j++) o[i][j] = 0.0f;
    }
    __syncthreads();

    for (int kt = 0; kt < S_ / TS; kt++) {
        int t0 = kt * TS;
        for (int i = tid; i < TS * 16; i += 256) {
            int r = i >> 4, f = (i & 15) << 2;
            *(float4*)&KPs[r * TSTRIDE + f] =
                *(const float4*)(Kb + (size_t)(t0 + r) * (HKV_ * D_) + f);
            *(float4*)&Vs[r * TSTRIDE + f] =
                *(const float4*)(Vb + (size_t)(t0 + r) * (HKV_ * D_) + f);
        }
        __syncthreads();

        // S = (Q/8) @ K^T  -> sc[4][4]
        float sc[4][4];
#pragma unroll
        for (int i = 0; i < 4; i++)
#pragma unroll
            for (int j = 0; j < 4; j++) sc[i][j] = 0.0f;

        for (int kk = 0; kk < TS; kk += 4) {
            float4 qa[4], kb[4];
#pragma unroll
            for (int i = 0; i < 4; i++)
                qa[i] = *(const float4*)&Qs[(ty * 4 + i) * TSTRIDE + kk];
#pragma unroll
            for (int j = 0; j < 4; j++)
                kb[j] = *(const float4*)&KPs[(tx * 4 + j) * TSTRIDE + kk];
#pragma unroll
            for (int i = 0; i < 4; i++)
#pragma unroll
                for (int j = 0; j < 4; j++) {
                    sc[i][j] = fmaf(qa[i].x, kb[j].x, sc[i][j]);
                    sc[i][j] = fmaf(qa[i].y, kb[j].y, sc[i][j]);
                    sc[i][j] = fmaf(qa[i].z, kb[j].z, sc[i][j]);
                    sc[i][j] = fmaf(qa[i].w, kb[j].w, sc[i][j]);
                }
        }
        __syncthreads();   // everyone done reading K before P overwrites it

        // Online softmax (row groups = 16 lanes sharing same ty)
#pragma unroll
        for (int i = 0; i < 4; i++) {
            float mx = fmaxf(fmaxf(sc[i][0], sc[i][1]), fmaxf(sc[i][2], sc[i][3]));
#pragma unroll
            for (int off = 1; off < 16; off <<= 1)
                mx = fmaxf(mx, __shfl_xor_sync(0xffffffffu, mx, off));
            float nm = fmaxf(mst[i], mx);
            float corr = __expf(mst[i] - nm);
            mst[i] = nm;
            float ps = 0.0f;
#pragma unroll
            for (int j = 0; j < 4; j++) {
                float p = __expf(sc[i][j] - nm);
                sc[i][j] = p;
                ps += p;
            }
#pragma unroll
            for (int off = 1; off < 16; off <<= 1)
                ps += __shfl_xor_sync(0xffffffffu, ps, off);
            lst[i] = lst[i] * corr + ps;
#pragma unroll
            for (int j = 0; j < 4; j++) o[i][j] *= corr;
            // stash P into KPs
            *(float4*)&KPs[(ty * 4 + i) * TSTRIDE + tx * 4] =
                make_float4(sc[i][0], sc[i][1], sc[i][2], sc[i][3]);
        }
        __syncthreads();

        // O += P @ V
        for (int k = 0; k < TS; k += 4) {
            float4 p4[4], v4[4];
#pragma unroll
            for (int i = 0; i < 4; i++)
                p4[i] = *(const float4*)&KPs[(ty * 4 + i) * TSTRIDE + k];
#pragma unroll
            for (int kk = 0; kk < 4; kk++)
                v4[kk] = *(const float4*)&Vs[(k + kk) * TSTRIDE + tx * 4];
#pragma unroll
            for (int i = 0; i < 4; i++) {
                float pv[4] = {p4[i].x, p4[i].y, p4[i].z, p4[i].w};
                float vv[4][4] = {
                    {v4[0].x, v4[0].y, v4[0].z, v4[0].w},
                    {v4[1].x, v4[1].y, v4[1].z, v4[1].w},
                    {v4[2].x, v4[2].y, v4[2].z, v4[2].w},
                    {v4[3].x, v4[3].y, v4[3].z, v4[3].w}};
#pragma unroll
                for (int j = 0; j < 4; j++) {
                    o[i][j] = fmaf(pv[0], vv[0][j], o[i][j]);
                    o[i][j] = fmaf(pv[1], vv[1][j], o[i][j]);
                    o[i][j] = fmaf(pv[2], vv[2][j], o[i][j]);
                    o[i][j] = fmaf(pv[3], vv[3][j], o[i][j]);
                }
            }
        }
        __syncthreads();   // done reading KPs/Vs before next tile load
    }

    // Epilogue: normalize, write (B,S,H*D)
    float* Ob = g_attn + ((size_t)b * S_ + s0) * E_ + h * D_;
#pragma unroll
    for (int i = 0; i < 4; i++) {
        float inv = 1.0f / lst[i];
        *(float4*)(Ob + (size_t)(ty * 4 + i) * E_ + tx * 4) =
            make_float4(o[i][0] * inv, o[i][1] * inv, o[i][2] * inv, o[i][3] * inv);
    }
}

// ---------------------------------------------------------------------------
// Launch
// ---------------------------------------------------------------------------
extern "C" void kernel_launch(void* const* d_in, const int* in_sizes, int n_in,
                              void* d_out, int out_size)
{
    const float* x    = (const float*)d_in[0];
    const float* cosT = (const float*)d_in[1];
    const float* sinT = (const float*)d_in[2];
    const float* Wq   = (const float*)d_in[3];
    const float* Wk   = (const float*)d_in[4];
    const float* Wv   = (const float*)d_in[5];
    const float* Wo   = (const float*)d_in[6];
    float* out = (float*)d_out;

    float *Qp, *Kp, *Vp, *Ap;
    cudaGetSymbolAddress((void**)&Qp, g_Q);
    cudaGetSymbolAddress((void**)&Kp, g_K);
    cudaGetSymbolAddress((void**)&Vp, g_V);
    cudaGetSymbolAddress((void**)&Ap, g_attn);

    const int M = B_ * S_;   // 4096

    // QKV projections
    gemm_nt_kernel<<<dim3(E_ / 128, M / 128), 256>>>(x, Wq, Qp, M, E_, E_);
    gemm_nt_kernel<<<dim3((HKV_ * D_) / 128, M / 128), 256>>>(x, Wk, Kp, M, HKV_ * D_, E_);
    gemm_nt_kernel<<<dim3((HKV_ * D_) / 128, M / 128), 256>>>(x, Wv, Vp, M, HKV_ * D_, E_);

    // RoPE on Q and K
    {
        int totQ = B_ * S_ * H_ * (D_ / 2);
        rope_kernel<<<(totQ + 255) / 256, 256>>>(Qp, cosT, sinT, H_);
        int totK = B_ * S_ * HKV_ * (D_ / 2);
        rope_kernel<<<(totK + 255) / 256, 256>>>(Kp, cosT, sinT, HKV_);
    }

    // Attention
    {
        size_t smem = 3 * TS * TSTRIDE * sizeof(float);  // 52,224 B
        cudaFuncSetAttribute(attn_kernel,
                             cudaFuncAttributeMaxDynamicSharedMemorySize,
                             (int)smem);
        attn_kernel<<<dim3(S_ / TS, H_, B_), 256, smem>>>();
    }

    // Output projection -> d_out
    gemm_nt_kernel<<<dim3(E_ / 128, M / 128), 256>>>(Ap, Wo, out, M, E_, E_);
}

// round 4
// speedup vs baseline: 1.2049x; 1.2049x over previous
#include <cuda_runtime.h>
#include <cuda_bf16.h>
#include <cstddef>
#include <cstdint>

#define B_   2
#define S_   2048
#define E_   2048
#define H_   32
#define HKV_ 8
#define D_   64
#define G_   4

// ---------------------------------------------------------------------------
// Scratch (zero-init .bss, no allocation)
// ---------------------------------------------------------------------------
__device__ float g_Q[(size_t)B_ * S_ * E_];            // (B,S,H*D) after Q proj
__device__ float g_K[(size_t)B_ * S_ * HKV_ * D_];     // (B,S,HKV*D)
__device__ float g_V[(size_t)B_ * S_ * HKV_ * D_];
__device__ float g_attn[(size_t)B_ * S_ * E_];         // (B,S,H*D) attention out

// split-bf16 copies of GEMM operands
__device__ __nv_bfloat16 g_x_hi[(size_t)B_ * S_ * E_];
__device__ __nv_bfloat16 g_x_lo[(size_t)B_ * S_ * E_];
__device__ __nv_bfloat16 g_Wq_hi[(size_t)E_ * E_];
__device__ __nv_bfloat16 g_Wq_lo[(size_t)E_ * E_];
__device__ __nv_bfloat16 g_Wk_hi[(size_t)HKV_ * D_ * E_];
__device__ __nv_bfloat16 g_Wk_lo[(size_t)HKV_ * D_ * E_];
__device__ __nv_bfloat16 g_Wv_hi[(size_t)HKV_ * D_ * E_];
__device__ __nv_bfloat16 g_Wv_lo[(size_t)HKV_ * D_ * E_];
__device__ __nv_bfloat16 g_Wo_hi[(size_t)E_ * E_];
__device__ __nv_bfloat16 g_Wo_lo[(size_t)E_ * E_];
__device__ __nv_bfloat16 g_attn_hi[(size_t)B_ * S_ * E_];
__device__ __nv_bfloat16 g_attn_lo[(size_t)B_ * S_ * E_];

// ---------------------------------------------------------------------------
// fp32 -> (hi, lo) bf16 split
// ---------------------------------------------------------------------------
__global__ void split_kernel(const float* __restrict__ src,
                             __nv_bfloat16* __restrict__ hi,
                             __nv_bfloat16* __restrict__ lo, int n)
{
    int i = blockIdx.x * blockDim.x + threadIdx.x;
    if (i >= n) return;
    float a = src[i];
    __nv_bfloat16 h = __float2bfloat16(a);
    hi[i] = h;
    lo[i] = __float2bfloat16(a - __bfloat162float(h));
}

// ---------------------------------------------------------------------------
// Split-bf16 NT GEMM via mma.sync.m16n8k16:
// C[M,N] = A[M,K] @ B[N,K]^T where a = a_hi + a_lo, using
// a*b ~= ahi*bhi + ahi*blo + alo*bhi  (fp32 accumulate)
// BM=128, BN=128, BK=32, 256 threads (8 warps, 2x4), warp tile 64x32.
// ---------------------------------------------------------------------------
#define SKS 48   // smem row stride in halves (96B, 16B-aligned)

__device__ __forceinline__ void mma16816(float* c, const unsigned* a, const unsigned* b)
{
    asm volatile(
        "mma.sync.aligned.m16n8k16.row.col.f32.bf16.bf16.f32 "
        "{%0,%1,%2,%3}, {%4,%5,%6,%7}, {%8,%9}, {%0,%1,%2,%3};\n"
        : "+f"(c[0]), "+f"(c[1]), "+f"(c[2]), "+f"(c[3])
        : "r"(a[0]), "r"(a[1]), "r"(a[2]), "r"(a[3]), "r"(b[0]), "r"(b[1]));
}

__global__ __launch_bounds__(256) void gemm_split_nt_kernel(
    const __nv_bfloat16* __restrict__ Ahi, const __nv_bfloat16* __restrict__ Alo,
    const __nv_bfloat16* __restrict__ Bhi, const __nv_bfloat16* __restrict__ Blo,
    float* __restrict__ C, int M, int N, int K)
{
    __shared__ __nv_bfloat16 sAhi[128 * SKS];
    __shared__ __nv_bfloat16 sAlo[128 * SKS];
    __shared__ __nv_bfloat16 sBhi[128 * SKS];
    __shared__ __nv_bfloat16 sBlo[128 * SKS];

    int tid  = threadIdx.x;
    int lane = tid & 31;
    int wid  = tid >> 5;
    int wm = wid & 1;          // 0..1  (M dir, 64 rows each)
    int wn = wid >> 1;         // 0..3  (N dir, 32 cols each)
    int g  = lane >> 2;        // 0..7
    int t2 = (lane & 3) * 2;   // 0,2,4,6

    int m0 = blockIdx.y * 128;
    int n0 = blockIdx.x * 128;

    float acc[4][4][4];
#pragma unroll
    for (int i = 0; i < 4; i++)
#pragma unroll
        for (int j = 0; j < 4; j++)
#pragma unroll
            for (int r = 0; r < 4; r++) acc[i][j][r] = 0.0f;

    // gmem->smem mapping: each thread copies one 16B chunk (8 bf16) per row-pass
    int lr = tid >> 2;              // 0..63
    int lc = (tid & 3) * 8;         // 0,8,16,24 (halves within 32-col tile)

    for (int k0 = 0; k0 < K; k0 += 32) {
#pragma unroll
        for (int rr = 0; rr < 2; rr++) {
            int row = lr + rr * 64;
            size_t ga = (size_t)(m0 + row) * K + k0 + lc;
            size_t gb = (size_t)(n0 + row) * K + k0 + lc;
            *(uint4*)&sAhi[row * SKS + lc] = *(const uint4*)&Ahi[ga];
            *(uint4*)&sAlo[row * SKS + lc] = *(const uint4*)&Alo[ga];
            *(uint4*)&sBhi[row * SKS + lc] = *(const uint4*)&Bhi[gb];
            *(uint4*)&sBlo[row * SKS + lc] = *(const uint4*)&Blo[gb];
        }
        __syncthreads();

#pragma unroll
        for (int ks = 0; ks < 32; ks += 16) {
            unsigned ah[4][4], al[4][4], bh[4][2], bl[4][2];
#pragma unroll
            for (int mi = 0; mi < 4; mi++) {
                int mb = wm * 64 + mi * 16;
                ah[mi][0] = *(const unsigned*)&sAhi[(mb + g) * SKS + ks + t2];
                ah[mi][1] = *(const unsigned*)&sAhi[(mb + g + 8) * SKS + ks + t2];
                ah[mi][2] = *(const unsigned*)&sAhi[(mb + g) * SKS + ks + 8 + t2];
                ah[mi][3] = *(const unsigned*)&sAhi[(mb + g + 8) * SKS + ks + 8 + t2];
                al[mi][0] = *(const unsigned*)&sAlo[(mb + g) * SKS + ks + t2];
                al[mi][1] = *(const unsigned*)&sAlo[(mb + g + 8) * SKS + ks + t2];
                al[mi][2] = *(const unsigned*)&sAlo[(mb + g) * SKS + ks + 8 + t2];
                al[mi][3] = *(const unsigned*)&sAlo[(mb + g + 8) * SKS + ks + 8 + t2];
            }
#pragma unroll
            for (int ni = 0; ni < 4; ni++) {
                int nb = wn * 32 + ni * 8;
                bh[ni][0] = *(const unsigned*)&sBhi[(nb + g) * SKS + ks + t2];
                bh[ni][1] = *(const unsigned*)&sBhi[(nb + g) * SKS + ks + 8 + t2];
                bl[ni][0] = *(const unsigned*)&sBlo[(nb + g) * SKS + ks + t2];
                bl[ni][1] = *(const unsigned*)&sBlo[(nb + g) * SKS + ks + 8 + t2];
            }
#pragma unroll
            for (int mi = 0; mi < 4; mi++)
#pragma unroll
                for (int ni = 0; ni < 4; ni++) {
                    mma16816(acc[mi][ni], ah[mi], bh[ni]);
                    mma16816(acc[mi][ni], ah[mi], bl[ni]);
                    mma16816(acc[mi][ni], al[mi], bh[ni]);
                }
        }
        __syncthreads();
    }

    // Epilogue
#pragma unroll
    for (int mi = 0; mi < 4; mi++) {
#pragma unroll
        for (int ni = 0; ni < 4; ni++) {
            int row = m0 + wm * 64 + mi * 16 + g;
            int col = n0 + wn * 32 + ni * 8 + t2;
            *(float2*)&C[(size_t)row * N + col] =
                make_float2(acc[mi][ni][0], acc[mi][ni][1]);
            *(float2*)&C[(size_t)(row + 8) * N + col] =
                make_float2(acc[mi][ni][2], acc[mi][ni][3]);
        }
    }
}

// ---------------------------------------------------------------------------
// RoPE (in place): buf is (B,S,nheads,D).
// ---------------------------------------------------------------------------
__global__ void rope_kernel(float* __restrict__ buf,
                            const float* __restrict__ cosT,
                            const float* __restrict__ sinT, int nheads)
{
    int idx = blockIdx.x * blockDim.x + threadIdx.x;
    int total = B_ * S_ * nheads * (D_ / 2);
    if (idx >= total) return;
    int d = idx & 31;
    int h = (idx >> 5) % nheads;
    int m = idx / (32 * nheads);
    int s = m % S_;
    size_t base = (size_t)m * nheads * D_ + h * D_;
    float q0 = buf[base + d];
    float q1 = buf[base + d + 32];
    float c0 = cosT[s * D_ + d],      s0 = sinT[s * D_ + d];
    float c1 = cosT[s * D_ + d + 32], s1 = sinT[s * D_ + d + 32];
    buf[base + d]      = q0 * c0 - q1 * s0;
    buf[base + d + 32] = q1 * c1 + q0 * s1;
}

// ---------------------------------------------------------------------------
// Flash attention (non-causal), Br=Bc=64, D=64, fp32, online softmax.
// ---------------------------------------------------------------------------
#define TS 64
#define TSTRIDE 68

__global__ __launch_bounds__(256) void attn_kernel()
{
    extern __shared__ float sm[];
    float* Qs  = sm;
    float* KPs = sm + TS * TSTRIDE;
    float* Vs  = sm + 2 * TS * TSTRIDE;

    int tid = threadIdx.x;
    int ty = tid >> 4, tx = tid & 15;
    int qt = blockIdx.x, h = blockIdx.y, b = blockIdx.z;
    int kvh = h >> 2;
    int s0 = qt * TS;

    const float* Qb = g_Q + ((size_t)b * S_ + s0) * E_ + h * D_;
    const float* Kb = g_K + (size_t)b * S_ * (HKV_ * D_) + kvh * D_;
    const float* Vb = g_V + (size_t)b * S_ * (HKV_ * D_) + kvh * D_;

    for (int i = tid; i < TS * 16; i += 256) {
        int r = i >> 4, f = (i & 15) << 2;
        float4 v = *(const float4*)(Qb + (size_t)r * E_ + f);
        v.x *= 0.125f; v.y *= 0.125f; v.z *= 0.125f; v.w *= 0.125f;
        *(float4*)&Qs[r * TSTRIDE + f] = v;
    }

    float mst[4], lst[4], o[4][4];
#pragma unroll
    for (int i = 0; i < 4; i++) {
        mst[i] = -1e30f; lst[i] = 0.0f;
#pragma unroll
        for (int j = 0; j < 4; j++) o[i][j] = 0.0f;
    }
    __syncthreads();

    for (int kt = 0; kt < S_ / TS; kt++) {
        int t0 = kt * TS;
        for (int i = tid; i < TS * 16; i += 256) {
            int r = i >> 4, f = (i & 15) << 2;
            *(float4*)&KPs[r * TSTRIDE + f] =
                *(const float4*)(Kb + (size_t)(t0 + r) * (HKV_ * D_) + f);
            *(float4*)&Vs[r * TSTRIDE + f] =
                *(const float4*)(Vb + (size_t)(t0 + r) * (HKV_ * D_) + f);
        }
        __syncthreads();

        float sc[4][4];
#pragma unroll
        for (int i = 0; i < 4; i++)
#pragma unroll
            for (int j = 0; j < 4; j++) sc[i][j] = 0.0f;

        for (int kk = 0; kk < TS; kk += 4) {
            float4 qa[4], kb[4];
#pragma unroll
            for (int i = 0; i < 4; i++)
                qa[i] = *(const float4*)&Qs[(ty * 4 + i) * TSTRIDE + kk];
#pragma unroll
            for (int j = 0; j < 4; j++)
                kb[j] = *(const float4*)&KPs[(tx * 4 + j) * TSTRIDE + kk];
#pragma unroll
            for (int i = 0; i < 4; i++)
#pragma unroll
                for (int j = 0; j < 4; j++) {
                    sc[i][j] = fmaf(qa[i].x, kb[j].x, sc[i][j]);
                    sc[i][j] = fmaf(qa[i].y, kb[j].y, sc[i][j]);
                    sc[i][j] = fmaf(qa[i].z, kb[j].z, sc[i][j]);
                    sc[i][j] = fmaf(qa[i].w, kb[j].w, sc[i][j]);
                }
        }
        __syncthreads();

#pragma unroll
        for (int i = 0; i < 4; i++) {
            float mx = fmaxf(fmaxf(sc[i][0], sc[i][1]), fmaxf(sc[i][2], sc[i][3]));
#pragma unroll
            for (int off = 1; off < 16; off <<= 1)
                mx = fmaxf(mx, __shfl_xor_sync(0xffffffffu, mx, off));
            float nm = fmaxf(mst[i], mx);
            float corr = __expf(mst[i] - nm);
            mst[i] = nm;
            float ps = 0.0f;
#pragma unroll
            for (int j = 0; j < 4; j++) {
                float p = __expf(sc[i][j] - nm);
                sc[i][j] = p;
                ps += p;
            }
#pragma unroll
            for (int off = 1; off < 16; off <<= 1)
                ps += __shfl_xor_sync(0xffffffffu, ps, off);
            lst[i] = lst[i] * corr + ps;
#pragma unroll
            for (int j = 0; j < 4; j++) o[i][j] *= corr;
            *(float4*)&KPs[(ty * 4 + i) * TSTRIDE + tx * 4] =
                make_float4(sc[i][0], sc[i][1], sc[i][2], sc[i][3]);
        }
        __syncthreads();

        for (int k = 0; k < TS; k += 4) {
            float4 p4[4], v4[4];
#pragma unroll
            for (int i = 0; i < 4; i++)
                p4[i] = *(const float4*)&KPs[(ty * 4 + i) * TSTRIDE + k];
#pragma unroll
            for (int kk = 0; kk < 4; kk++)
                v4[kk] = *(const float4*)&Vs[(k + kk) * TSTRIDE + tx * 4];
#pragma unroll
            for (int i = 0; i < 4; i++) {
                float pv[4] = {p4[i].x, p4[i].y, p4[i].z, p4[i].w};
                float vv[4][4] = {
                    {v4[0].x, v4[0].y, v4[0].z, v4[0].w},
                    {v4[1].x, v4[1].y, v4[1].z, v4[1].w},
                    {v4[2].x, v4[2].y, v4[2].z, v4[2].w},
                    {v4[3].x, v4[3].y, v4[3].z, v4[3].w}};
#pragma unroll
                for (int j = 0; j < 4; j++) {
                    o[i][j] = fmaf(pv[0], vv[0][j], o[i][j]);
                    o[i][j] = fmaf(pv[1], vv[1][j], o[i][j]);
                    o[i][j] = fmaf(pv[2], vv[2][j], o[i][j]);
                    o[i][j] = fmaf(pv[3], vv[3][j], o[i][j]);
                }
            }
        }
        __syncthreads();
    }

    float* Ob = g_attn + ((size_t)b * S_ + s0) * E_ + h * D_;
#pragma unroll
    for (int i = 0; i < 4; i++) {
        float inv = 1.0f / lst[i];
        *(float4*)(Ob + (size_t)(ty * 4 + i) * E_ + tx * 4) =
            make_float4(o[i][0] * inv, o[i][1] * inv, o[i][2] * inv, o[i][3] * inv);
    }
}

// ---------------------------------------------------------------------------
// Launch
// ---------------------------------------------------------------------------
extern "C" void kernel_launch(void* const* d_in, const int* in_sizes, int n_in,
                              void* d_out, int out_size)
{
    const float* x    = (const float*)d_in[0];
    const float* cosT = (const float*)d_in[1];
    const float* sinT = (const float*)d_in[2];
    const float* Wq   = (const float*)d_in[3];
    const float* Wk   = (const float*)d_in[4];
    const float* Wv   = (const float*)d_in[5];
    const float* Wo   = (const float*)d_in[6];
    float* out = (float*)d_out;

    float *Qp, *Kp, *Vp, *Ap;
    __nv_bfloat16 *xh, *xl, *qh, *ql, *kh, *kl, *vh, *vl, *oh, *ol, *ah, *al;
    cudaGetSymbolAddress((void**)&Qp, g_Q);
    cudaGetSymbolAddress((void**)&Kp, g_K);
    cudaGetSymbolAddress((void**)&Vp, g_V);
    cudaGetSymbolAddress((void**)&Ap, g_attn);
    cudaGetSymbolAddress((void**)&xh, g_x_hi);  cudaGetSymbolAddress((void**)&xl, g_x_lo);
    cudaGetSymbolAddress((void**)&qh, g_Wq_hi); cudaGetSymbolAddress((void**)&ql, g_Wq_lo);
    cudaGetSymbolAddress((void**)&kh, g_Wk_hi); cudaGetSymbolAddress((void**)&kl, g_Wk_lo);
    cudaGetSymbolAddress((void**)&vh, g_Wv_hi); cudaGetSymbolAddress((void**)&vl, g_Wv_lo);
    cudaGetSymbolAddress((void**)&oh, g_Wo_hi); cudaGetSymbolAddress((void**)&ol, g_Wo_lo);
    cudaGetSymbolAddress((void**)&ah, g_attn_hi); cudaGetSymbolAddress((void**)&al, g_attn_lo);

    const int M = B_ * S_;   // 4096

    // Split conversions
    {
        int nx = M * E_;
        split_kernel<<<(nx + 255) / 256, 256>>>(x, xh, xl, nx);
        int nq = E_ * E_;
        split_kernel<<<(nq + 255) / 256, 256>>>(Wq, qh, ql, nq);
        int nk = HKV_ * D_ * E_;
        split_kernel<<<(nk + 255) / 256, 256>>>(Wk, kh, kl, nk);
        split_kernel<<<(nk + 255) / 256, 256>>>(Wv, vh, vl, nk);
        split_kernel<<<(nq + 255) / 256, 256>>>(Wo, oh, ol, nq);
    }

    // QKV projections (split-bf16 tensor-core GEMMs)
    gemm_split_nt_kernel<<<dim3(E_ / 128, M / 128), 256>>>(xh, xl, qh, ql, Qp, M, E_, E_);
    gemm_split_nt_kernel<<<dim3((HKV_ * D_) / 128, M / 128), 256>>>(xh, xl, kh, kl, Kp, M, HKV_ * D_, E_);
    gemm_split_nt_kernel<<<dim3((HKV_ * D_) / 128, M / 128), 256>>>(xh, xl, vh, vl, Vp, M, HKV_ * D_, E_);

    // RoPE on Q and K
    {
        int totQ = B_ * S_ * H_ * (D_ / 2);
        rope_kernel<<<(totQ + 255) / 256, 256>>>(Qp, cosT, sinT, H_);
        int totK = B_ * S_ * HKV_ * (D_ / 2);
        rope_kernel<<<(totK + 255) / 256, 256>>>(Kp, cosT, sinT, HKV_);
    }

    // Attention
    {
        size_t smem = 3 * TS * TSTRIDE * sizeof(float);
        cudaFuncSetAttribute(attn_kernel,
                             cudaFuncAttributeMaxDynamicSharedMemorySize,
                             (int)smem);
        attn_kernel<<<dim3(S_ / TS, H_, B_), 256, smem>>>();
    }

    // Split attention output, then output projection -> d_out
    {
        int na = M * E_;
        split_kernel<<<(na + 255) / 256, 256>>>(Ap, ah, al, na);
    }
    gemm_split_nt_kernel<<<dim3(E_ / 128, M / 128), 256>>>(ah, al, oh, ol, out, M, E_, E_);
}

// round 6
// speedup vs baseline: 2.7640x; 2.2939x over previous
#include <cuda_runtime.h>
#include <cuda_bf16.h>
#include <cstddef>
#include <cstdint>

#define B_   2
#define S_   2048
#define E_   2048
#define H_   32
#define HKV_ 8
#define D_   64
#define G_   4
#define KVW  (HKV_ * D_)    // 512

// ---------------------------------------------------------------------------
// Scratch (zero-init .bss, no allocation)
// ---------------------------------------------------------------------------
__device__ float g_Q[(size_t)B_ * S_ * E_];            // fp32 Q proj (pre-rope)
__device__ float g_K[(size_t)B_ * S_ * KVW];
__device__ float g_V[(size_t)B_ * S_ * KVW];

// split-bf16 operands
__device__ __nv_bfloat16 g_x_hi[(size_t)B_ * S_ * E_];
__device__ __nv_bfloat16 g_x_lo[(size_t)B_ * S_ * E_];
__device__ __nv_bfloat16 g_Wq_hi[(size_t)E_ * E_];
__device__ __nv_bfloat16 g_Wq_lo[(size_t)E_ * E_];
__device__ __nv_bfloat16 g_Wk_hi[(size_t)KVW * E_];
__device__ __nv_bfloat16 g_Wk_lo[(size_t)KVW * E_];
__device__ __nv_bfloat16 g_Wv_hi[(size_t)KVW * E_];
__device__ __nv_bfloat16 g_Wv_lo[(size_t)KVW * E_];
__device__ __nv_bfloat16 g_Wo_hi[(size_t)E_ * E_];
__device__ __nv_bfloat16 g_Wo_lo[(size_t)E_ * E_];

// split-bf16 Q/K/V for attention (Q pre-scaled by 1/8, rope applied)
__device__ __nv_bfloat16 g_Qbh[(size_t)B_ * S_ * E_];
__device__ __nv_bfloat16 g_Qbl[(size_t)B_ * S_ * E_];
__device__ __nv_bfloat16 g_Kbh[(size_t)B_ * S_ * KVW];
__device__ __nv_bfloat16 g_Kbl[(size_t)B_ * S_ * KVW];
__device__ __nv_bfloat16 g_Vbh[(size_t)B_ * S_ * KVW];
__device__ __nv_bfloat16 g_Vbl[(size_t)B_ * S_ * KVW];

// attention output (split, fed to final GEMM)
__device__ __nv_bfloat16 g_attn_hi[(size_t)B_ * S_ * E_];
__device__ __nv_bfloat16 g_attn_lo[(size_t)B_ * S_ * E_];

// ---------------------------------------------------------------------------
// helpers
// ---------------------------------------------------------------------------
__device__ __forceinline__ unsigned packbf(float lo, float hi)
{
    unsigned r;
    asm("cvt.rn.bf16x2.f32 %0, %1, %2;" : "=r"(r) : "f"(hi), "f"(lo));
    return r;
}
// split (x,y) fp32 pair into bf16x2 hi and lo-residual parts
__device__ __forceinline__ void split2(float x, float y, unsigned& hi, unsigned& lo)
{
    hi = packbf(x, y);
    float xh = __uint_as_float(hi << 16);
    float yh = __uint_as_float(hi & 0xffff0000u);
    lo = packbf(x - xh, y - yh);
}

__device__ __forceinline__ void mma16816(float* c, const unsigned* a, const unsigned* b)
{
    asm volatile(
        "mma.sync.aligned.m16n8k16.row.col.f32.bf16.bf16.f32 "
        "{%0,%1,%2,%3}, {%4,%5,%6,%7}, {%8,%9}, {%0,%1,%2,%3};\n"
        : "+f"(c[0]), "+f"(c[1]), "+f"(c[2]), "+f"(c[3])
        : "r"(a[0]), "r"(a[1]), "r"(a[2]), "r"(a[3]), "r"(b[0]), "r"(b[1]));
}

__device__ __forceinline__ void ldmx2t(unsigned& r0, unsigned& r1, const __nv_bfloat16* p)
{
    unsigned addr = (unsigned)__cvta_generic_to_shared(p);
    asm volatile("ldmatrix.sync.aligned.m8n8.x2.trans.shared.b16 {%0,%1}, [%2];"
                 : "=r"(r0), "=r"(r1) : "r"(addr));
}

// ---------------------------------------------------------------------------
// fp32 -> (hi, lo) bf16 split
// ---------------------------------------------------------------------------
__global__ void split_kernel(const float* __restrict__ src,
                             __nv_bfloat16* __restrict__ hi,
                             __nv_bfloat16* __restrict__ lo, int n)
{
    int i = blockIdx.x * blockDim.x + threadIdx.x;
    if (i >= n) return;
    float a = src[i];
    __nv_bfloat16 h = __float2bfloat16(a);
    hi[i] = h;
    lo[i] = __float2bfloat16(a - __bfloat162float(h));
}

// ---------------------------------------------------------------------------
// RoPE + scale + split: fp32 (B,S,nh,D) -> bf16 hi/lo
// ---------------------------------------------------------------------------
__global__ void rope_split_kernel(const float* __restrict__ buf,
                                  const float* __restrict__ cosT,
                                  const float* __restrict__ sinT,
                                  int nheads, float scale,
                                  __nv_bfloat16* __restrict__ hi,
                                  __nv_bfloat16* __restrict__ lo)
{
    int idx = blockIdx.x * blockDim.x + threadIdx.x;
    int total = B_ * S_ * nheads * (D_ / 2);
    if (idx >= total) return;
    int d = idx & 31;
    int h = (idx >> 5) % nheads;
    int m = idx / (32 * nheads);
    int s = m % S_;
    size_t base = (size_t)m * nheads * D_ + h * D_;
    float q0 = buf[base + d];
    float q1 = buf[base + d + 32];
    float c0 = cosT[s * D_ + d],      s0 = sinT[s * D_ + d];
    float c1 = cosT[s * D_ + d + 32], s1 = sinT[s * D_ + d + 32];
    float r0 = (q0 * c0 - q1 * s0) * scale;
    float r1 = (q1 * c1 + q0 * s1) * scale;
    __nv_bfloat16 h0 = __float2bfloat16(r0);
    __nv_bfloat16 h1 = __float2bfloat16(r1);
    hi[base + d]      = h0;
    hi[base + d + 32] = h1;
    lo[base + d]      = __float2bfloat16(r0 - __bfloat162float(h0));
    lo[base + d + 32] = __float2bfloat16(r1 - __bfloat162float(h1));
}

// ---------------------------------------------------------------------------
// Split-bf16 NT GEMM via mma.sync.m16n8k16 (unchanged from R4)
// ---------------------------------------------------------------------------
#define SKS 48

__global__ __launch_bounds__(256) void gemm_split_nt_kernel(
    const __nv_bfloat16* __restrict__ Ahi, const __nv_bfloat16* __restrict__ Alo,
    const __nv_bfloat16* __restrict__ Bhi, const __nv_bfloat16* __restrict__ Blo,
    float* __restrict__ C, int M, int N, int K)
{
    __shared__ __nv_bfloat16 sAhi[128 * SKS];
    __shared__ __nv_bfloat16 sAlo[128 * SKS];
    __shared__ __nv_bfloat16 sBhi[128 * SKS];
    __shared__ __nv_bfloat16 sBlo[128 * SKS];

    int tid  = threadIdx.x;
    int lane = tid & 31;
    int wid  = tid >> 5;
    int wm = wid & 1;
    int wn = wid >> 1;
    int g  = lane >> 2;
    int t2 = (lane & 3) * 2;

    int m0 = blockIdx.y * 128;
    int n0 = blockIdx.x * 128;

    float acc[4][4][4];
#pragma unroll
    for (int i = 0; i < 4; i++)
#pragma unroll
        for (int j = 0; j < 4; j++)
#pragma unroll
            for (int r = 0; r < 4; r++) acc[i][j][r] = 0.0f;

    int lr = tid >> 2;
    int lc = (tid & 3) * 8;

    for (int k0 = 0; k0 < K; k0 += 32) {
#pragma unroll
        for (int rr = 0; rr < 2; rr++) {
            int row = lr + rr * 64;
            size_t ga = (size_t)(m0 + row) * K + k0 + lc;
            size_t gb = (size_t)(n0 + row) * K + k0 + lc;
            *(uint4*)&sAhi[row * SKS + lc] = *(const uint4*)&Ahi[ga];
            *(uint4*)&sAlo[row * SKS + lc] = *(const uint4*)&Alo[ga];
            *(uint4*)&sBhi[row * SKS + lc] = *(const uint4*)&Bhi[gb];
            *(uint4*)&sBlo[row * SKS + lc] = *(const uint4*)&Blo[gb];
        }
        __syncthreads();

#pragma unroll
        for (int ks = 0; ks < 32; ks += 16) {
            unsigned ah[4][4], al[4][4], bh[4][2], bl[4][2];
#pragma unroll
            for (int mi = 0; mi < 4; mi++) {
                int mb = wm * 64 + mi * 16;
                ah[mi][0] = *(const unsigned*)&sAhi[(mb + g) * SKS + ks + t2];
                ah[mi][1] = *(const unsigned*)&sAhi[(mb + g + 8) * SKS + ks + t2];
                ah[mi][2] = *(const unsigned*)&sAhi[(mb + g) * SKS + ks + 8 + t2];
                ah[mi][3] = *(const unsigned*)&sAhi[(mb + g + 8) * SKS + ks + 8 + t2];
                al[mi][0] = *(const unsigned*)&sAlo[(mb + g) * SKS + ks + t2];
                al[mi][1] = *(const unsigned*)&sAlo[(mb + g + 8) * SKS + ks + t2];
                al[mi][2] = *(const unsigned*)&sAlo[(mb + g) * SKS + ks + 8 + t2];
                al[mi][3] = *(const unsigned*)&sAlo[(mb + g + 8) * SKS + ks + 8 + t2];
            }
#pragma unroll
            for (int ni = 0; ni < 4; ni++) {
                int nb = wn * 32 + ni * 8;
                bh[ni][0] = *(const unsigned*)&sBhi[(nb + g) * SKS + ks + t2];
                bh[ni][1] = *(const unsigned*)&sBhi[(nb + g) * SKS + ks + 8 + t2];
                bl[ni][0] = *(const unsigned*)&sBlo[(nb + g) * SKS + ks + t2];
                bl[ni][1] = *(const unsigned*)&sBlo[(nb + g) * SKS + ks + 8 + t2];
            }
#pragma unroll
            for (int mi = 0; mi < 4; mi++)
#pragma unroll
                for (int ni = 0; ni < 4; ni++) {
                    mma16816(acc[mi][ni], ah[mi], bh[ni]);
                    mma16816(acc[mi][ni], ah[mi], bl[ni]);
                    mma16816(acc[mi][ni], al[mi], bh[ni]);
                }
        }
        __syncthreads();
    }

#pragma unroll
    for (int mi = 0; mi < 4; mi++) {
#pragma unroll
        for (int ni = 0; ni < 4; ni++) {
            int row = m0 + wm * 64 + mi * 16 + g;
            int col = n0 + wn * 32 + ni * 8 + t2;
            *(float2*)&C[(size_t)row * N + col] =
                make_float2(acc[mi][ni][0], acc[mi][ni][1]);
            *(float2*)&C[(size_t)(row + 8) * N + col] =
                make_float2(acc[mi][ni][2], acc[mi][ni][3]);
        }
    }
}

// ---------------------------------------------------------------------------
// Tensor-core flash attention, split-bf16, Br=128, Bc=64, D=64.
// 8 warps; warp w owns q-rows [16w, 16w+16). Non-causal, online softmax.
// smem stride 72 bf16 (conflict-free for 32-bit fragment LDS).
// ---------------------------------------------------------------------------
#define AST 72

__global__ __launch_bounds__(256) void attn_mma_kernel()
{
    extern __shared__ __nv_bfloat16 smb[];
    __nv_bfloat16* sQh = smb;                 // 128 x 72
    __nv_bfloat16* sQl = smb + 128 * AST;
    __nv_bfloat16* sKh = smb + 256 * AST;     // 64 x 72
    __nv_bfloat16* sKl = smb + 320 * AST;
    __nv_bfloat16* sVh = smb + 384 * AST;     // 64 x 72 (row-major: key, d)
    __nv_bfloat16* sVl = smb + 448 * AST;

    int tid  = threadIdx.x;
    int lane = tid & 31;
    int wid  = tid >> 5;
    int g    = lane >> 2;
    int t2   = (lane & 3) * 2;
    int lrow = lane & 15;

    int qt = blockIdx.x, h = blockIdx.y, b = blockIdx.z;
    int kvh = h >> 2;
    int s0 = qt * 128;

    const __nv_bfloat16* Qhg = g_Qbh + ((size_t)(b * S_ + s0)) * E_ + h * D_;
    const __nv_bfloat16* Qlg = g_Qbl + ((size_t)(b * S_ + s0)) * E_ + h * D_;
    const __nv_bfloat16* Khg = g_Kbh + (size_t)b * S_ * KVW + kvh * D_;
    const __nv_bfloat16* Klg = g_Kbl + (size_t)b * S_ * KVW + kvh * D_;
    const __nv_bfloat16* Vhg = g_Vbh + (size_t)b * S_ * KVW + kvh * D_;
    const __nv_bfloat16* Vlg = g_Vbl + (size_t)b * S_ * KVW + kvh * D_;

    // Load Q tile (128 x 64, hi+lo)
    for (int c = tid; c < 1024; c += 256) {
        int r = c >> 3, col = (c & 7) * 8;
        *(uint4*)&sQh[r * AST + col] = *(const uint4*)&Qhg[(size_t)r * E_ + col];
        *(uint4*)&sQl[r * AST + col] = *(const uint4*)&Qlg[(size_t)r * E_ + col];
    }

    int wr = wid * 16;              // warp's q-row base in tile
    float m0r = -1e30f, m1r = -1e30f, l0r = 0.0f, l1r = 0.0f;
    float O[8][4];
#pragma unroll
    for (int nt = 0; nt < 8; nt++)
#pragma unroll
        for (int r = 0; r < 4; r++) O[nt][r] = 0.0f;

    for (int kt0 = 0; kt0 < S_ / 64; kt0++) {
        int t0 = kt0 * 64;
        // Load K,V tiles (64 x 64 each, hi+lo)
        for (int c = tid; c < 512; c += 256) {
            int r = c >> 3, col = (c & 7) * 8;
            size_t ga = (size_t)(t0 + r) * KVW + col;
            *(uint4*)&sKh[r * AST + col] = *(const uint4*)&Khg[ga];
            *(uint4*)&sKl[r * AST + col] = *(const uint4*)&Klg[ga];
            *(uint4*)&sVh[r * AST + col] = *(const uint4*)&Vhg[ga];
            *(uint4*)&sVl[r * AST + col] = *(const uint4*)&Vlg[ga];
        }
        __syncthreads();

        // ---- S = Q @ K^T (fp32 accum via 3-term split) ----
        float acc[8][4];
#pragma unroll
        for (int nt = 0; nt < 8; nt++)
#pragma unroll
            for (int r = 0; r < 4; r++) acc[nt][r] = 0.0f;

#pragma unroll
        for (int kt = 0; kt < 4; kt++) {
            int k0 = kt * 16;
            unsigned ah[4], al[4];
            ah[0] = *(const unsigned*)&sQh[(wr + g) * AST + k0 + t2];
            ah[1] = *(const unsigned*)&sQh[(wr + g + 8) * AST + k0 + t2];
            ah[2] = *(const unsigned*)&sQh[(wr + g) * AST + k0 + 8 + t2];
            ah[3] = *(const unsigned*)&sQh[(wr + g + 8) * AST + k0 + 8 + t2];
            al[0] = *(const unsigned*)&sQl[(wr + g) * AST + k0 + t2];
            al[1] = *(const unsigned*)&sQl[(wr + g + 8) * AST + k0 + t2];
            al[2] = *(const unsigned*)&sQl[(wr + g) * AST + k0 + 8 + t2];
            al[3] = *(const unsigned*)&sQl[(wr + g + 8) * AST + k0 + 8 + t2];
#pragma unroll
            for (int nt = 0; nt < 8; nt++) {
                unsigned bh[2], bl[2];
                bh[0] = *(const unsigned*)&sKh[(nt * 8 + g) * AST + k0 + t2];
                bh[1] = *(const unsigned*)&sKh[(nt * 8 + g) * AST + k0 + 8 + t2];
                bl[0] = *(const unsigned*)&sKl[(nt * 8 + g) * AST + k0 + t2];
                bl[1] = *(const unsigned*)&sKl[(nt * 8 + g) * AST + k0 + 8 + t2];
                mma16816(acc[nt], ah, bh);
                mma16816(acc[nt], ah, bl);
                mma16816(acc[nt], al, bh);
            }
        }

        // ---- online softmax ----
        float mx0 = -1e30f, mx1 = -1e30f;
#pragma unroll
        for (int nt = 0; nt < 8; nt++) {
            mx0 = fmaxf(mx0, fmaxf(acc[nt][0], acc[nt][1]));
            mx1 = fmaxf(mx1, fmaxf(acc[nt][2], acc[nt][3]));
        }
        mx0 = fmaxf(mx0, __shfl_xor_sync(0xffffffffu, mx0, 1));
        mx0 = fmaxf(mx0, __shfl_xor_sync(0xffffffffu, mx0, 2));
        mx1 = fmaxf(mx1, __shfl_xor_sync(0xffffffffu, mx1, 1));
        mx1 = fmaxf(mx1, __shfl_xor_sync(0xffffffffu, mx1, 2));
        float nm0 = fmaxf(m0r, mx0), nm1 = fmaxf(m1r, mx1);
        float corr0 = __expf(m0r - nm0), corr1 = __expf(m1r - nm1);
        m0r = nm0; m1r = nm1;

        float sum0 = 0.0f, sum1 = 0.0f;
#pragma unroll
        for (int nt = 0; nt < 8; nt++) {
            acc[nt][0] = __expf(acc[nt][0] - nm0); sum0 += acc[nt][0];
            acc[nt][1] = __expf(acc[nt][1] - nm0); sum0 += acc[nt][1];
            acc[nt][2] = __expf(acc[nt][2] - nm1); sum1 += acc[nt][2];
            acc[nt][3] = __expf(acc[nt][3] - nm1); sum1 += acc[nt][3];
        }
        sum0 += __shfl_xor_sync(0xffffffffu, sum0, 1);
        sum0 += __shfl_xor_sync(0xffffffffu, sum0, 2);
        sum1 += __shfl_xor_sync(0xffffffffu, sum1, 1);
        sum1 += __shfl_xor_sync(0xffffffffu, sum1, 2);
        l0r = l0r * corr0 + sum0;
        l1r = l1r * corr1 + sum1;
#pragma unroll
        for (int nt = 0; nt < 8; nt++) {
            O[nt][0] *= corr0; O[nt][1] *= corr0;
            O[nt][2] *= corr1; O[nt][3] *= corr1;
        }

        // ---- O += P @ V (3-term split; P packed in registers) ----
#pragma unroll
        for (int kt = 0; kt < 4; kt++) {
            unsigned ph[4], pl[4];
            split2(acc[2 * kt][0],     acc[2 * kt][1],     ph[0], pl[0]);
            split2(acc[2 * kt][2],     acc[2 * kt][3],     ph[1], pl[1]);
            split2(acc[2 * kt + 1][0], acc[2 * kt + 1][1], ph[2], pl[2]);
            split2(acc[2 * kt + 1][2], acc[2 * kt + 1][3], ph[3], pl[3]);
            const __nv_bfloat16* vh_base = sVh + (kt * 16 + lrow) * AST;
            const __nv_bfloat16* vl_base = sVl + (kt * 16 + lrow) * AST;
#pragma unroll
            for (int nt = 0; nt < 8; nt++) {
                unsigned bh[2], bl[2];
                ldmx2t(bh[0], bh[1], vh_base + nt * 8);
                ldmx2t(bl[0], bl[1], vl_base + nt * 8);
                mma16816(O[nt], ph, bh);
                mma16816(O[nt], ph, bl);
                mma16816(O[nt], pl, bh);
            }
        }
        __syncthreads();
    }

    // ---- epilogue: normalize, split to bf16 hi/lo, write ----
    float inv0 = 1.0f / l0r, inv1 = 1.0f / l1r;
    size_t row0 = (size_t)(b * S_ + s0 + wr + g) * E_ + h * D_;
    size_t row1 = (size_t)(b * S_ + s0 + wr + g + 8) * E_ + h * D_;
#pragma unroll
    for (int nt = 0; nt < 8; nt++) {
        unsigned hi, lo;
        split2(O[nt][0] * inv0, O[nt][1] * inv0, hi, lo);
        *(unsigned*)&g_attn_hi[row0 + nt * 8 + t2] = hi;
        *(unsigned*)&g_attn_lo[row0 + nt * 8 + t2] = lo;
        split2(O[nt][2] * inv1, O[nt][3] * inv1, hi, lo);
        *(unsigned*)&g_attn_hi[row1 + nt * 8 + t2] = hi;
        *(unsigned*)&g_attn_lo[row1 + nt * 8 + t2] = lo;
    }
}

// ---------------------------------------------------------------------------
// Launch
// ---------------------------------------------------------------------------
extern "C" void kernel_launch(void* const* d_in, const int* in_sizes, int n_in,
                              void* d_out, int out_size)
{
    const float* x    = (const float*)d_in[0];
    const float* cosT = (const float*)d_in[1];
    const float* sinT = (const float*)d_in[2];
    const float* Wq   = (const float*)d_in[3];
    const float* Wk   = (const float*)d_in[4];
    const float* Wv   = (const float*)d_in[5];
    const float* Wo   = (const float*)d_in[6];
    float* out = (float*)d_out;

    float *Qp, *Kp, *Vp;
    __nv_bfloat16 *xh, *xl, *qh, *ql, *kh, *kl, *vh, *vl, *oh, *ol;
    __nv_bfloat16 *qbh, *qbl, *kbh, *kbl, *vbh, *vbl, *ah, *al;
    cudaGetSymbolAddress((void**)&Qp, g_Q);
    cudaGetSymbolAddress((void**)&Kp, g_K);
    cudaGetSymbolAddress((void**)&Vp, g_V);
    cudaGetSymbolAddress((void**)&xh, g_x_hi);  cudaGetSymbolAddress((void**)&xl, g_x_lo);
    cudaGetSymbolAddress((void**)&qh, g_Wq_hi); cudaGetSymbolAddress((void**)&ql, g_Wq_lo);
    cudaGetSymbolAddress((void**)&kh, g_Wk_hi); cudaGetSymbolAddress((void**)&kl, g_Wk_lo);
    cudaGetSymbolAddress((void**)&vh, g_Wv_hi); cudaGetSymbolAddress((void**)&vl, g_Wv_lo);
    cudaGetSymbolAddress((void**)&oh, g_Wo_hi); cudaGetSymbolAddress((void**)&ol, g_Wo_lo);
    cudaGetSymbolAddress((void**)&qbh, g_Qbh);  cudaGetSymbolAddress((void**)&qbl, g_Qbl);
    cudaGetSymbolAddress((void**)&kbh, g_Kbh);  cudaGetSymbolAddress((void**)&kbl, g_Kbl);
    cudaGetSymbolAddress((void**)&vbh, g_Vbh);  cudaGetSymbolAddress((void**)&vbl, g_Vbl);
    cudaGetSymbolAddress((void**)&ah, g_attn_hi); cudaGetSymbolAddress((void**)&al, g_attn_lo);

    const int M = B_ * S_;   // 4096

    // Split conversions (inputs + weights)
    {
        int nx = M * E_;
        split_kernel<<<(nx + 255) / 256, 256>>>(x, xh, xl, nx);
        int nq = E_ * E_;
        split_kernel<<<(nq + 255) / 256, 256>>>(Wq, qh, ql, nq);
        int nk = KVW * E_;
        split_kernel<<<(nk + 255) / 256, 256>>>(Wk, kh, kl, nk);
        split_kernel<<<(nk + 255) / 256, 256>>>(Wv, vh, vl, nk);
        split_kernel<<<(nq + 255) / 256, 256>>>(Wo, oh, ol, nq);
    }

    // QKV projections
    gemm_split_nt_kernel<<<dim3(E_ / 128, M / 128), 256>>>(xh, xl, qh, ql, Qp, M, E_, E_);
    gemm_split_nt_kernel<<<dim3(KVW / 128, M / 128), 256>>>(xh, xl, kh, kl, Kp, M, KVW, E_);
    gemm_split_nt_kernel<<<dim3(KVW / 128, M / 128), 256>>>(xh, xl, vh, vl, Vp, M, KVW, E_);

    // RoPE + scale + split (Q scaled by 1/sqrt(D)); V plain split
    {
        int totQ = B_ * S_ * H_ * (D_ / 2);
        rope_split_kernel<<<(totQ + 255) / 256, 256>>>(Qp, cosT, sinT, H_, 0.125f, qbh, qbl);
        int totK = B_ * S_ * HKV_ * (D_ / 2);
        rope_split_kernel<<<(totK + 255) / 256, 256>>>(Kp, cosT, sinT, HKV_, 1.0f, kbh, kbl);
        int nv = M * KVW;
        split_kernel<<<(nv + 255) / 256, 256>>>(Vp, vbh, vbl, nv);
    }

    // Tensor-core flash attention -> split bf16 output
    {
        size_t smem = 512 * AST * sizeof(__nv_bfloat16);  // 73,728 B
        cudaFuncSetAttribute(attn_mma_kernel,
                             cudaFuncAttributeMaxDynamicSharedMemorySize,
                             (int)smem);
        attn_mma_kernel<<<dim3(S_ / 128, H_, B_), 256, smem>>>();
    }

    // Output projection -> d_out
    gemm_split_nt_kernel<<<dim3(E_ / 128, M / 128), 256>>>(ah, al, oh, ol, out, M, E_, E_);
}

// round 8
// speedup vs baseline: 3.2298x; 1.1686x over previous
#include <cuda_runtime.h>
#include <cuda_bf16.h>
#include <cstddef>
#include <cstdint>

#define B_   2
#define S_   2048
#define E_   2048
#define H_   32
#define HKV_ 8
#define D_   64
#define G_   4
#define KVW  (HKV_ * D_)    // 512

// ---------------------------------------------------------------------------
// Scratch (zero-init .bss, no allocation)
// ---------------------------------------------------------------------------
__device__ float g_Q[(size_t)B_ * S_ * E_];
__device__ float g_K[(size_t)B_ * S_ * KVW];
__device__ float g_V[(size_t)B_ * S_ * KVW];

__device__ __nv_bfloat16 g_x_hi[(size_t)B_ * S_ * E_];
__device__ __nv_bfloat16 g_x_lo[(size_t)B_ * S_ * E_];
__device__ __nv_bfloat16 g_Wq_hi[(size_t)E_ * E_];
__device__ __nv_bfloat16 g_Wq_lo[(size_t)E_ * E_];
__device__ __nv_bfloat16 g_Wk_hi[(size_t)KVW * E_];
__device__ __nv_bfloat16 g_Wk_lo[(size_t)KVW * E_];
__device__ __nv_bfloat16 g_Wv_hi[(size_t)KVW * E_];
__device__ __nv_bfloat16 g_Wv_lo[(size_t)KVW * E_];
__device__ __nv_bfloat16 g_Wo_hi[(size_t)E_ * E_];
__device__ __nv_bfloat16 g_Wo_lo[(size_t)E_ * E_];

__device__ __nv_bfloat16 g_Qbh[(size_t)B_ * S_ * E_];
__device__ __nv_bfloat16 g_Qbl[(size_t)B_ * S_ * E_];
__device__ __nv_bfloat16 g_Kbh[(size_t)B_ * S_ * KVW];
__device__ __nv_bfloat16 g_Kbl[(size_t)B_ * S_ * KVW];
__device__ __nv_bfloat16 g_Vbh[(size_t)B_ * S_ * KVW];
__device__ __nv_bfloat16 g_Vbl[(size_t)B_ * S_ * KVW];

__device__ __nv_bfloat16 g_attn_hi[(size_t)B_ * S_ * E_];
__device__ __nv_bfloat16 g_attn_lo[(size_t)B_ * S_ * E_];

// ---------------------------------------------------------------------------
// helpers
// ---------------------------------------------------------------------------
__device__ __forceinline__ unsigned packbf(float lo, float hi)
{
    unsigned r;
    asm("cvt.rn.bf16x2.f32 %0, %1, %2;" : "=r"(r) : "f"(hi), "f"(lo));
    return r;
}
__device__ __forceinline__ void split2(float x, float y, unsigned& hi, unsigned& lo)
{
    hi = packbf(x, y);
    float xh = __uint_as_float(hi << 16);
    float yh = __uint_as_float(hi & 0xffff0000u);
    lo = packbf(x - xh, y - yh);
}

__device__ __forceinline__ void mma16816(float* c, const unsigned* a, const unsigned* b)
{
    asm volatile(
        "mma.sync.aligned.m16n8k16.row.col.f32.bf16.bf16.f32 "
        "{%0,%1,%2,%3}, {%4,%5,%6,%7}, {%8,%9}, {%0,%1,%2,%3};\n"
        : "+f"(c[0]), "+f"(c[1]), "+f"(c[2]), "+f"(c[3])
        : "r"(a[0]), "r"(a[1]), "r"(a[2]), "r"(a[3]), "r"(b[0]), "r"(b[1]));
}
__device__ __forceinline__ void mma16816_b2(float* c, const unsigned* a,
                                            unsigned b0, unsigned b1)
{
    asm volatile(
        "mma.sync.aligned.m16n8k16.row.col.f32.bf16.bf16.f32 "
        "{%0,%1,%2,%3}, {%4,%5,%6,%7}, {%8,%9}, {%0,%1,%2,%3};\n"
        : "+f"(c[0]), "+f"(c[1]), "+f"(c[2]), "+f"(c[3])
        : "r"(a[0]), "r"(a[1]), "r"(a[2]), "r"(a[3]), "r"(b0), "r"(b1));
}

__device__ __forceinline__ void ldmx2t(unsigned& r0, unsigned& r1, const __nv_bfloat16* p)
{
    unsigned addr = (unsigned)__cvta_generic_to_shared(p);
    asm volatile("ldmatrix.sync.aligned.m8n8.x2.trans.shared.b16 {%0,%1}, [%2];"
                 : "=r"(r0), "=r"(r1) : "r"(addr));
}
__device__ __forceinline__ void ldmx4(unsigned* r, const __nv_bfloat16* p)
{
    unsigned addr = (unsigned)__cvta_generic_to_shared(p);
    asm volatile("ldmatrix.sync.aligned.m8n8.x4.shared.b16 {%0,%1,%2,%3}, [%4];"
                 : "=r"(r[0]), "=r"(r[1]), "=r"(r[2]), "=r"(r[3]) : "r"(addr));
}
__device__ __forceinline__ void cpasync16(__nv_bfloat16* smem, const __nv_bfloat16* gmem)
{
    unsigned s = (unsigned)__cvta_generic_to_shared(smem);
    asm volatile("cp.async.cg.shared.global [%0], [%1], 16;" :: "r"(s), "l"(gmem));
}

// ---------------------------------------------------------------------------
// fp32 -> (hi, lo) bf16 split
// ---------------------------------------------------------------------------
__global__ void split_kernel(const float* __restrict__ src,
                             __nv_bfloat16* __restrict__ hi,
                             __nv_bfloat16* __restrict__ lo, int n)
{
    int i = blockIdx.x * blockDim.x + threadIdx.x;
    if (i >= n) return;
    float a = src[i];
    __nv_bfloat16 h = __float2bfloat16(a);
    hi[i] = h;
    lo[i] = __float2bfloat16(a - __bfloat162float(h));
}

// ---------------------------------------------------------------------------
// RoPE + scale + split
// ---------------------------------------------------------------------------
__global__ void rope_split_kernel(const float* __restrict__ buf,
                                  const float* __restrict__ cosT,
                                  const float* __restrict__ sinT,
                                  int nheads, float scale,
                                  __nv_bfloat16* __restrict__ hi,
                                  __nv_bfloat16* __restrict__ lo)
{
    int idx = blockIdx.x * blockDim.x + threadIdx.x;
    int total = B_ * S_ * nheads * (D_ / 2);
    if (idx >= total) return;
    int d = idx & 31;
    int h = (idx >> 5) % nheads;
    int m = idx / (32 * nheads);
    int s = m % S_;
    size_t base = (size_t)m * nheads * D_ + h * D_;
    float q0 = buf[base + d];
    float q1 = buf[base + d + 32];
    float c0 = cosT[s * D_ + d],      s0 = sinT[s * D_ + d];
    float c1 = cosT[s * D_ + d + 32], s1 = sinT[s * D_ + d + 32];
    float r0 = (q0 * c0 - q1 * s0) * scale;
    float r1 = (q1 * c1 + q0 * s1) * scale;
    __nv_bfloat16 h0 = __float2bfloat16(r0);
    __nv_bfloat16 h1 = __float2bfloat16(r1);
    hi[base + d]      = h0;
    hi[base + d + 32] = h1;
    lo[base + d]      = __float2bfloat16(r0 - __bfloat162float(h0));
    lo[base + d + 32] = __float2bfloat16(r1 - __bfloat162float(h1));
}

// ---------------------------------------------------------------------------
// Split-bf16 NT GEMM, cp.async 2-stage pipeline + ldmatrix fragments.
// BM=128, BN=128, BK=32, 256 threads (8 warps 2x4), warp tile 64x32.
// smem row stride 40 halves (80B): ldmatrix 8-row phase hits word banks
// {0,20,8,28,16,4,24,12} -> conflict-free.
// ---------------------------------------------------------------------------
#define GST 40
#define MATSZ (128 * GST)           // halves per matrix per stage
#define STSZ  (4 * MATSZ)           // halves per stage

__global__ __launch_bounds__(256) void gemm_split_nt2_kernel(
    const __nv_bfloat16* __restrict__ Ahi, const __nv_bfloat16* __restrict__ Alo,
    const __nv_bfloat16* __restrict__ Bhi, const __nv_bfloat16* __restrict__ Blo,
    float* __restrict__ C, int M, int N, int K)
{
    extern __shared__ __nv_bfloat16 smg[];   // 2 stages x 4 matrices x 128x40

    int tid  = threadIdx.x;
    int lane = tid & 31;
    int wid  = tid >> 5;
    int wm = wid & 1;
    int wn = wid >> 1;
    int g  = lane >> 2;
    int t2 = (lane & 3) * 2;

    int m0 = blockIdx.y * 128;
    int n0 = blockIdx.x * 128;

    int crow = tid >> 2;           // 0..63
    int cchk = (tid & 3) * 8;      // halves

    float acc[4][4][4];
#pragma unroll
    for (int i = 0; i < 4; i++)
#pragma unroll
        for (int j = 0; j < 4; j++)
#pragma unroll
            for (int r = 0; r < 4; r++) acc[i][j][r] = 0.0f;

    auto stage_load = [&](int k0, int s) {
        __nv_bfloat16* base = smg + s * STSZ;
#pragma unroll
        for (int rr = 0; rr < 2; rr++) {
            int row = crow + rr * 64;
            size_t ga = (size_t)(m0 + row) * K + k0 + cchk;
            size_t gb = (size_t)(n0 + row) * K + k0 + cchk;
            int so = row * GST + cchk;
            cpasync16(base + so,             Ahi + ga);
            cpasync16(base + MATSZ + so,     Alo + ga);
            cpasync16(base + 2 * MATSZ + so, Bhi + gb);
            cpasync16(base + 3 * MATSZ + so, Blo + gb);
        }
    };

    int niter = K / 32;
    stage_load(0, 0);
    asm volatile("cp.async.commit_group;" ::: "memory");
    stage_load(32, 1);
    asm volatile("cp.async.commit_group;" ::: "memory");

    // ldmatrix per-lane source rows/cols
    int l16 = lane & 15;
    int lc8 = (lane >> 4) * 8;

    for (int it = 0; it < niter; it++) {
        asm volatile("cp.async.wait_group 1;" ::: "memory");
        __syncthreads();

        __nv_bfloat16* base = smg + (it & 1) * STSZ;
        __nv_bfloat16* sAh = base;
        __nv_bfloat16* sAl = base + MATSZ;
        __nv_bfloat16* sBh = base + 2 * MATSZ;
        __nv_bfloat16* sBl = base + 3 * MATSZ;

#pragma unroll
        for (int ks = 0; ks < 32; ks += 16) {
            unsigned ah[4][4], al[4][4];
            int acol = ks + lc8;
#pragma unroll
            for (int mi = 0; mi < 4; mi++) {
                int ar = wm * 64 + mi * 16 + l16;
                ldmx4(ah[mi], sAh + ar * GST + acol);
                ldmx4(al[mi], sAl + ar * GST + acol);
            }
#pragma unroll
            for (int np = 0; np < 2; np++) {
                unsigned bh4[4], bl4[4];
                int br = wn * 32 + np * 16 + l16;
                ldmx4(bh4, sBh + br * GST + acol);
                ldmx4(bl4, sBl + br * GST + acol);
#pragma unroll
                for (int mi = 0; mi < 4; mi++) {
                    mma16816_b2(acc[mi][2 * np],     ah[mi], bh4[0], bh4[2]);
                    mma16816_b2(acc[mi][2 * np],     ah[mi], bl4[0], bl4[2]);
                    mma16816_b2(acc[mi][2 * np],     al[mi], bh4[0], bh4[2]);
                    mma16816_b2(acc[mi][2 * np + 1], ah[mi], bh4[1], bh4[3]);
                    mma16816_b2(acc[mi][2 * np + 1], ah[mi], bl4[1], bl4[3]);
                    mma16816_b2(acc[mi][2 * np + 1], al[mi], bh4[1], bh4[3]);
                }
            }
        }
        __syncthreads();
        if (it + 2 < niter) stage_load((it + 2) * 32, it & 1);
        asm volatile("cp.async.commit_group;" ::: "memory");
    }

#pragma unroll
    for (int mi = 0; mi < 4; mi++) {
#pragma unroll
        for (int ni = 0; ni < 4; ni++) {
            int row = m0 + wm * 64 + mi * 16 + g;
            int col = n0 + wn * 32 + ni * 8 + t2;
            *(float2*)&C[(size_t)row * N + col] =
                make_float2(acc[mi][ni][0], acc[mi][ni][1]);
            *(float2*)&C[(size_t)(row + 8) * N + col] =
                make_float2(acc[mi][ni][2], acc[mi][ni][3]);
        }
    }
}

// ---------------------------------------------------------------------------
// Tensor-core flash attention (unchanged from R6)
// ---------------------------------------------------------------------------
#define AST 72

__global__ __launch_bounds__(256) void attn_mma_kernel()
{
    extern __shared__ __nv_bfloat16 smb[];
    __nv_bfloat16* sQh = smb;
    __nv_bfloat16* sQl = smb + 128 * AST;
    __nv_bfloat16* sKh = smb + 256 * AST;
    __nv_bfloat16* sKl = smb + 320 * AST;
    __nv_bfloat16* sVh = smb + 384 * AST;
    __nv_bfloat16* sVl = smb + 448 * AST;

    int tid  = threadIdx.x;
    int lane = tid & 31;
    int wid  = tid >> 5;
    int g    = lane >> 2;
    int t2   = (lane & 3) * 2;
    int lrow = lane & 15;

    int qt = blockIdx.x, h = blockIdx.y, b = blockIdx.z;
    int kvh = h >> 2;
    int s0 = qt * 128;

    const __nv_bfloat16* Qhg = g_Qbh + ((size_t)(b * S_ + s0)) * E_ + h * D_;
    const __nv_bfloat16* Qlg = g_Qbl + ((size_t)(b * S_ + s0)) * E_ + h * D_;
    const __nv_bfloat16* Khg = g_Kbh + (size_t)b * S_ * KVW + kvh * D_;
    const __nv_bfloat16* Klg = g_Kbl + (size_t)b * S_ * KVW + kvh * D_;
    const __nv_bfloat16* Vhg = g_Vbh + (size_t)b * S_ * KVW + kvh * D_;
    const __nv_bfloat16* Vlg = g_Vbl + (size_t)b * S_ * KVW + kvh * D_;

    for (int c = tid; c < 1024; c += 256) {
        int r = c >> 3, col = (c & 7) * 8;
        *(uint4*)&sQh[r * AST + col] = *(const uint4*)&Qhg[(size_t)r * E_ + col];
        *(uint4*)&sQl[r * AST + col] = *(const uint4*)&Qlg[(size_t)r * E_ + col];
    }

    int wr = wid * 16;
    float m0r = -1e30f, m1r = -1e30f, l0r = 0.0f, l1r = 0.0f;
    float O[8][4];
#pragma unroll
    for (int nt = 0; nt < 8; nt++)
#pragma unroll
        for (int r = 0; r < 4; r++) O[nt][r] = 0.0f;

    for (int kt0 = 0; kt0 < S_ / 64; kt0++) {
        int t0 = kt0 * 64;
        for (int c = tid; c < 512; c += 256) {
            int r = c >> 3, col = (c & 7) * 8;
            size_t ga = (size_t)(t0 + r) * KVW + col;
            *(uint4*)&sKh[r * AST + col] = *(const uint4*)&Khg[ga];
            *(uint4*)&sKl[r * AST + col] = *(const uint4*)&Klg[ga];
            *(uint4*)&sVh[r * AST + col] = *(const uint4*)&Vhg[ga];
            *(uint4*)&sVl[r * AST + col] = *(const uint4*)&Vlg[ga];
        }
        __syncthreads();

        float acc[8][4];
#pragma unroll
        for (int nt = 0; nt < 8; nt++)
#pragma unroll
            for (int r = 0; r < 4; r++) acc[nt][r] = 0.0f;

#pragma unroll
        for (int kt = 0; kt < 4; kt++) {
            int k0 = kt * 16;
            unsigned ah[4], al[4];
            ah[0] = *(const unsigned*)&sQh[(wr + g) * AST + k0 + t2];
            ah[1] = *(const unsigned*)&sQh[(wr + g + 8) * AST + k0 + t2];
            ah[2] = *(const unsigned*)&sQh[(wr + g) * AST + k0 + 8 + t2];
            ah[3] = *(const unsigned*)&sQh[(wr + g + 8) * AST + k0 + 8 + t2];
            al[0] = *(const unsigned*)&sQl[(wr + g) * AST + k0 + t2];
            al[1] = *(const unsigned*)&sQl[(wr + g + 8) * AST + k0 + t2];
            al[2] = *(const unsigned*)&sQl[(wr + g) * AST + k0 + 8 + t2];
            al[3] = *(const unsigned*)&sQl[(wr + g + 8) * AST + k0 + 8 + t2];
#pragma unroll
            for (int nt = 0; nt < 8; nt++) {
                unsigned bh[2], bl[2];
                bh[0] = *(const unsigned*)&sKh[(nt * 8 + g) * AST + k0 + t2];
                bh[1] = *(const unsigned*)&sKh[(nt * 8 + g) * AST + k0 + 8 + t2];
                bl[0] = *(const unsigned*)&sKl[(nt * 8 + g) * AST + k0 + t2];
                bl[1] = *(const unsigned*)&sKl[(nt * 8 + g) * AST + k0 + 8 + t2];
                mma16816(acc[nt], ah, bh);
                mma16816(acc[nt], ah, bl);
                mma16816(acc[nt], al, bh);
            }
        }

        float mx0 = -1e30f, mx1 = -1e30f;
#pragma unroll
        for (int nt = 0; nt < 8; nt++) {
            mx0 = fmaxf(mx0, fmaxf(acc[nt][0], acc[nt][1]));
            mx1 = fmaxf(mx1, fmaxf(acc[nt][2], acc[nt][3]));
        }
        mx0 = fmaxf(mx0, __shfl_xor_sync(0xffffffffu, mx0, 1));
        mx0 = fmaxf(mx0, __shfl_xor_sync(0xffffffffu, mx0, 2));
        mx1 = fmaxf(mx1, __shfl_xor_sync(0xffffffffu, mx1, 1));
        mx1 = fmaxf(mx1, __shfl_xor_sync(0xffffffffu, mx1, 2));
        float nm0 = fmaxf(m0r, mx0), nm1 = fmaxf(m1r, mx1);
        float corr0 = __expf(m0r - nm0), corr1 = __expf(m1r - nm1);
        m0r = nm0; m1r = nm1;

        float sum0 = 0.0f, sum1 = 0.0f;
#pragma unroll
        for (int nt = 0; nt < 8; nt++) {
            acc[nt][0] = __expf(acc[nt][0] - nm0); sum0 += acc[nt][0];
            acc[nt][1] = __expf(acc[nt][1] - nm0); sum0 += acc[nt][1];
            acc[nt][2] = __expf(acc[nt][2] - nm1); sum1 += acc[nt][2];
            acc[nt][3] = __expf(acc[nt][3] - nm1); sum1 += acc[nt][3];
        }
        sum0 += __shfl_xor_sync(0xffffffffu, sum0, 1);
        sum0 += __shfl_xor_sync(0xffffffffu, sum0, 2);
        sum1 += __shfl_xor_sync(0xffffffffu, sum1, 1);
        sum1 += __shfl_xor_sync(0xffffffffu, sum1, 2);
        l0r = l0r * corr0 + sum0;
        l1r = l1r * corr1 + sum1;
#pragma unroll
        for (int nt = 0; nt < 8; nt++) {
            O[nt][0] *= corr0; O[nt][1] *= corr0;
            O[nt][2] *= corr1; O[nt][3] *= corr1;
        }

#pragma unroll
        for (int kt = 0; kt < 4; kt++) {
            unsigned ph[4], pl[4];
            split2(acc[2 * kt][0],     acc[2 * kt][1],     ph[0], pl[0]);
            split2(acc[2 * kt][2],     acc[2 * kt][3],     ph[1], pl[1]);
            split2(acc[2 * kt + 1][0], acc[2 * kt + 1][1], ph[2], pl[2]);
            split2(acc[2 * kt + 1][2], acc[2 * kt + 1][3], ph[3], pl[3]);
            const __nv_bfloat16* vh_base = sVh + (kt * 16 + lrow) * AST;
            const __nv_bfloat16* vl_base = sVl + (kt * 16 + lrow) * AST;
#pragma unroll
            for (int nt = 0; nt < 8; nt++) {
                unsigned bh[2], bl[2];
                ldmx2t(bh[0], bh[1], vh_base + nt * 8);
                ldmx2t(bl[0], bl[1], vl_base + nt * 8);
                mma16816(O[nt], ph, bh);
                mma16816(O[nt], ph, bl);
                mma16816(O[nt], pl, bh);
            }
        }
        __syncthreads();
    }

    float inv0 = 1.0f / l0r, inv1 = 1.0f / l1r;
    size_t row0 = (size_t)(b * S_ + s0 + wr + g) * E_ + h * D_;
    size_t row1 = (size_t)(b * S_ + s0 + wr + g + 8) * E_ + h * D_;
#pragma unroll
    for (int nt = 0; nt < 8; nt++) {
        unsigned hi, lo;
        split2(O[nt][0] * inv0, O[nt][1] * inv0, hi, lo);
        *(unsigned*)&g_attn_hi[row0 + nt * 8 + t2] = hi;
        *(unsigned*)&g_attn_lo[row0 + nt * 8 + t2] = lo;
        split2(O[nt][2] * inv1, O[nt][3] * inv1, hi, lo);
        *(unsigned*)&g_attn_hi[row1 + nt * 8 + t2] = hi;
        *(unsigned*)&g_attn_lo[row1 + nt * 8 + t2] = lo;
    }
}

// ---------------------------------------------------------------------------
// Launch
// ---------------------------------------------------------------------------
extern "C" void kernel_launch(void* const* d_in, const int* in_sizes, int n_in,
                              void* d_out, int out_size)
{
    const float* x    = (const float*)d_in[0];
    const float* cosT = (const float*)d_in[1];
    const float* sinT = (const float*)d_in[2];
    const float* Wq   = (const float*)d_in[3];
    const float* Wk   = (const float*)d_in[4];
    const float* Wv   = (const float*)d_in[5];
    const float* Wo   = (const float*)d_in[6];
    float* out = (float*)d_out;

    float *Qp, *Kp, *Vp;
    __nv_bfloat16 *xh, *xl, *qh, *ql, *kh, *kl, *vh, *vl, *oh, *ol;
    __nv_bfloat16 *qbh, *qbl, *kbh, *kbl, *vbh, *vbl, *ah, *al;
    cudaGetSymbolAddress((void**)&Qp, g_Q);
    cudaGetSymbolAddress((void**)&Kp, g_K);
    cudaGetSymbolAddress((void**)&Vp, g_V);
    cudaGetSymbolAddress((void**)&xh, g_x_hi);  cudaGetSymbolAddress((void**)&xl, g_x_lo);
    cudaGetSymbolAddress((void**)&qh, g_Wq_hi); cudaGetSymbolAddress((void**)&ql, g_Wq_lo);
    cudaGetSymbolAddress((void**)&kh, g_Wk_hi); cudaGetSymbolAddress((void**)&kl, g_Wk_lo);
    cudaGetSymbolAddress((void**)&vh, g_Wv_hi); cudaGetSymbolAddress((void**)&vl, g_Wv_lo);
    cudaGetSymbolAddress((void**)&oh, g_Wo_hi); cudaGetSymbolAddress((void**)&ol, g_Wo_lo);
    cudaGetSymbolAddress((void**)&qbh, g_Qbh);  cudaGetSymbolAddress((void**)&qbl, g_Qbl);
    cudaGetSymbolAddress((void**)&kbh, g_Kbh);  cudaGetSymbolAddress((void**)&kbl, g_Kbl);
    cudaGetSymbolAddress((void**)&vbh, g_Vbh);  cudaGetSymbolAddress((void**)&vbl, g_Vbl);
    cudaGetSymbolAddress((void**)&ah, g_attn_hi); cudaGetSymbolAddress((void**)&al, g_attn_lo);

    const int M = B_ * S_;   // 4096
    const size_t gsmem = 2 * STSZ * sizeof(__nv_bfloat16);  // 81,920 B

    static int configured = 0;
    if (!configured) {
        cudaFuncSetAttribute(gemm_split_nt2_kernel,
                             cudaFuncAttributeMaxDynamicSharedMemorySize, (int)gsmem);
        cudaFuncSetAttribute(attn_mma_kernel,
                             cudaFuncAttributeMaxDynamicSharedMemorySize,
                             512 * AST * sizeof(__nv_bfloat16));
        configured = 1;
    }

    // Split conversions
    {
        int nx = M * E_;
        split_kernel<<<(nx + 255) / 256, 256>>>(x, xh, xl, nx);
        int nq = E_ * E_;
        split_kernel<<<(nq + 255) / 256, 256>>>(Wq, qh, ql, nq);
        int nk = KVW * E_;
        split_kernel<<<(nk + 255) / 256, 256>>>(Wk, kh, kl, nk);
        split_kernel<<<(nk + 255) / 256, 256>>>(Wv, vh, vl, nk);
        split_kernel<<<(nq + 255) / 256, 256>>>(Wo, oh, ol, nq);
    }

    // QKV projections
    gemm_split_nt2_kernel<<<dim3(E_ / 128, M / 128), 256, gsmem>>>(xh, xl, qh, ql, Qp, M, E_, E_);
    gemm_split_nt2_kernel<<<dim3(KVW / 128, M / 128), 256, gsmem>>>(xh, xl, kh, kl, Kp, M, KVW, E_);
    gemm_split_nt2_kernel<<<dim3(KVW / 128, M / 128), 256, gsmem>>>(xh, xl, vh, vl, Vp, M, KVW, E_);

    // RoPE + scale + split; V plain split
    {
        int totQ = B_ * S_ * H_ * (D_ / 2);
        rope_split_kernel<<<(totQ + 255) / 256, 256>>>(Qp, cosT, sinT, H_, 0.125f, qbh, qbl);
        int totK = B_ * S_ * HKV_ * (D_ / 2);
        rope_split_kernel<<<(totK + 255) / 256, 256>>>(Kp, cosT, sinT, HKV_, 1.0f, kbh, kbl);
        int nv = M * KVW;
        split_kernel<<<(nv + 255) / 256, 256>>>(Vp, vbh, vbl, nv);
    }

    // Attention
    attn_mma_kernel<<<dim3(S_ / 128, H_, B_), 256,
                      512 * AST * sizeof(__nv_bfloat16)>>>();

    // Output projection -> d_out
    gemm_split_nt2_kernel<<<dim3(E_ / 128, M / 128), 256, gsmem>>>(ah, al, oh, ol, out, M, E_, E_);
}

// round 10
// speedup vs baseline: 3.3348x; 1.0325x over previous
#include <cuda_runtime.h>
#include <cuda_bf16.h>
#include <cstddef>
#include <cstdint>

#define B_   2
#define S_   2048
#define E_   2048
#define H_   32
#define HKV_ 8
#define D_   64
#define G_   4
#define KVW  (HKV_ * D_)    // 512
#define NQKV (E_ + 2 * KVW) // 3072

// ---------------------------------------------------------------------------
// Scratch (zero-init .bss, no allocation)
// ---------------------------------------------------------------------------
__device__ float g_QKV[(size_t)B_ * S_ * NQKV];       // fused QKV fp32 (pre-rope)

__device__ __nv_bfloat16 g_x_hi[(size_t)B_ * S_ * E_];
__device__ __nv_bfloat16 g_x_lo[(size_t)B_ * S_ * E_];
__device__ __nv_bfloat16 g_Wqkv_hi[(size_t)NQKV * E_];  // [Wq;Wk;Wv] rows
__device__ __nv_bfloat16 g_Wqkv_lo[(size_t)NQKV * E_];
__device__ __nv_bfloat16 g_Wo_hi[(size_t)E_ * E_];
__device__ __nv_bfloat16 g_Wo_lo[(size_t)E_ * E_];

__device__ __nv_bfloat16 g_Qbh[(size_t)B_ * S_ * E_];
__device__ __nv_bfloat16 g_Qbl[(size_t)B_ * S_ * E_];
__device__ __nv_bfloat16 g_Kbh[(size_t)B_ * S_ * KVW];
__device__ __nv_bfloat16 g_Kbl[(size_t)B_ * S_ * KVW];
__device__ __nv_bfloat16 g_Vbh[(size_t)B_ * S_ * KVW];
__device__ __nv_bfloat16 g_Vbl[(size_t)B_ * S_ * KVW];

__device__ __nv_bfloat16 g_attn_hi[(size_t)B_ * S_ * E_];
__device__ __nv_bfloat16 g_attn_lo[(size_t)B_ * S_ * E_];

// ---------------------------------------------------------------------------
// helpers
// ---------------------------------------------------------------------------
__device__ __forceinline__ unsigned smaddr(const void* p)
{
    return (unsigned)__cvta_generic_to_shared(p);
}
__device__ __forceinline__ unsigned packbf(float lo, float hi)
{
    unsigned r;
    asm("cvt.rn.bf16x2.f32 %0, %1, %2;" : "=r"(r) : "f"(hi), "f"(lo));
    return r;
}
__device__ __forceinline__ void split2(float x, float y, unsigned& hi, unsigned& lo)
{
    hi = packbf(x, y);
    float xh = __uint_as_float(hi << 16);
    float yh = __uint_as_float(hi & 0xffff0000u);
    lo = packbf(x - xh, y - yh);
}
__device__ __forceinline__ void mma16816(float* c, const unsigned* a, const unsigned* b)
{
    asm volatile(
        "mma.sync.aligned.m16n8k16.row.col.f32.bf16.bf16.f32 "
        "{%0,%1,%2,%3}, {%4,%5,%6,%7}, {%8,%9}, {%0,%1,%2,%3};\n"
        : "+f"(c[0]), "+f"(c[1]), "+f"(c[2]), "+f"(c[3])
        : "r"(a[0]), "r"(a[1]), "r"(a[2]), "r"(a[3]), "r"(b[0]), "r"(b[1]));
}
__device__ __forceinline__ void mma16816_b2(float* c, const unsigned* a,
                                            unsigned b0, unsigned b1)
{
    asm volatile(
        "mma.sync.aligned.m16n8k16.row.col.f32.bf16.bf16.f32 "
        "{%0,%1,%2,%3}, {%4,%5,%6,%7}, {%8,%9}, {%0,%1,%2,%3};\n"
        : "+f"(c[0]), "+f"(c[1]), "+f"(c[2]), "+f"(c[3])
        : "r"(a[0]), "r"(a[1]), "r"(a[2]), "r"(a[3]), "r"(b0), "r"(b1));
}
__device__ __forceinline__ void ldmx2t(unsigned& r0, unsigned& r1, const __nv_bfloat16* p)
{
    unsigned addr = smaddr(p);
    asm volatile("ldmatrix.sync.aligned.m8n8.x2.trans.shared.b16 {%0,%1}, [%2];"
                 : "=r"(r0), "=r"(r1) : "r"(addr));
}
__device__ __forceinline__ void ldmx4(unsigned* r, const __nv_bfloat16* p)
{
    unsigned addr = smaddr(p);
    asm volatile("ldmatrix.sync.aligned.m8n8.x4.shared.b16 {%0,%1,%2,%3}, [%4];"
                 : "=r"(r[0]), "=r"(r[1]), "=r"(r[2]), "=r"(r[3]) : "r"(addr));
}
__device__ __forceinline__ void cpasync16(void* smem, const void* gmem)
{
    unsigned s = smaddr(smem);
    asm volatile("cp.async.cg.shared.global [%0], [%1], 16;" :: "r"(s), "l"(gmem));
}

// ---------------------------------------------------------------------------
// fp32 -> (hi, lo) bf16 split (contiguous)
// ---------------------------------------------------------------------------
__global__ void split_kernel(const float* __restrict__ src,
                             __nv_bfloat16* __restrict__ hi,
                             __nv_bfloat16* __restrict__ lo, int n)
{
    int i = blockIdx.x * blockDim.x + threadIdx.x;
    if (i >= n) return;
    float a = src[i];
    __nv_bfloat16 h = __float2bfloat16(a);
    hi[i] = h;
    lo[i] = __float2bfloat16(a - __bfloat162float(h));
}

// strided split: out[m*ncols + c] = split(src[m*in_stride + c]), m<nrows
__global__ void split_strided_kernel(const float* __restrict__ src, int in_stride,
                                     int nrows, int ncols,
                                     __nv_bfloat16* __restrict__ hi,
                                     __nv_bfloat16* __restrict__ lo)
{
    int i = blockIdx.x * blockDim.x + threadIdx.x;
    if (i >= nrows * ncols) return;
    int m = i / ncols, c = i - m * ncols;
    float a = src[(size_t)m * in_stride + c];
    __nv_bfloat16 h = __float2bfloat16(a);
    hi[i] = h;
    lo[i] = __float2bfloat16(a - __bfloat162float(h));
}

// ---------------------------------------------------------------------------
// RoPE + scale + split (strided input)
// ---------------------------------------------------------------------------
__global__ void rope_split_kernel(const float* __restrict__ buf, int in_stride,
                                  const float* __restrict__ cosT,
                                  const float* __restrict__ sinT,
                                  int nheads, float scale,
                                  __nv_bfloat16* __restrict__ hi,
                                  __nv_bfloat16* __restrict__ lo)
{
    int idx = blockIdx.x * blockDim.x + threadIdx.x;
    int total = B_ * S_ * nheads * (D_ / 2);
    if (idx >= total) return;
    int d = idx & 31;
    int h = (idx >> 5) % nheads;
    int m = idx / (32 * nheads);
    int s = m % S_;
    size_t ibase = (size_t)m * in_stride + h * D_;
    size_t obase = (size_t)m * nheads * D_ + h * D_;
    float q0 = buf[ibase + d];
    float q1 = buf[ibase + d + 32];
    float c0 = cosT[s * D_ + d],      s0 = sinT[s * D_ + d];
    float c1 = cosT[s * D_ + d + 32], s1 = sinT[s * D_ + d + 32];
    float r0 = (q0 * c0 - q1 * s0) * scale;
    float r1 = (q1 * c1 + q0 * s1) * scale;
    __nv_bfloat16 h0 = __float2bfloat16(r0);
    __nv_bfloat16 h1 = __float2bfloat16(r1);
    hi[obase + d]      = h0;
    hi[obase + d + 32] = h1;
    lo[obase + d]      = __float2bfloat16(r0 - __bfloat162float(h0));
    lo[obase + d + 32] = __float2bfloat16(r1 - __bfloat162float(h1));
}

// ---------------------------------------------------------------------------
// Split-bf16 NT GEMM v3: BM=128, BN=256, BK=32, 3-stage cp.async, ldmatrix.
// 8 warps (2 M x 4 N), warp tile 64x64. smem stride 40 halves (conflict-free).
// ---------------------------------------------------------------------------
#define GST 40
#define ASZ (128 * GST)          // halves per A matrix per stage
#define BSZ (256 * GST)          // halves per B matrix per stage
#define STSZ (2 * ASZ + 2 * BSZ) // halves per stage (30720)
#define GEMM_SMEM (3 * STSZ * 2) // bytes (184320)

__global__ __launch_bounds__(256, 1) void gemm_split_nt3_kernel(
    const __nv_bfloat16* __restrict__ Ahi, const __nv_bfloat16* __restrict__ Alo,
    const __nv_bfloat16* __restrict__ Bhi, const __nv_bfloat16* __restrict__ Blo,
    float* __restrict__ C, int M, int N, int K)
{
    extern __shared__ __nv_bfloat16 smg[];   // 3 stages

    int tid  = threadIdx.x;
    int lane = tid & 31;
    int wid  = tid >> 5;
    int wm = wid & 1;            // 0..1
    int wn = wid >> 1;           // 0..3
    int g  = lane >> 2;
    int t2 = (lane & 3) * 2;
    int l16 = lane & 15;
    int lc8 = (lane >> 4) * 8;

    int m0 = blockIdx.y * 128;
    int n0 = blockIdx.x * 256;

    float acc[4][8][4];
#pragma unroll
    for (int i = 0; i < 4; i++)
#pragma unroll
        for (int j = 0; j < 8; j++)
#pragma unroll
            for (int r = 0; r < 4; r++) acc[i][j][r] = 0.0f;

    auto stage_load = [&](int k0, int s) {
        __nv_bfloat16* base = smg + s * STSZ;
        // A hi/lo: 128 rows x 32 cols -> 512 chunks each
#pragma unroll
        for (int c = tid; c < 512; c += 256) {
            int row = c >> 2, ch = (c & 3) * 8;
            size_t ga = (size_t)(m0 + row) * K + k0 + ch;
            int so = row * GST + ch;
            cpasync16(base + so,       Ahi + ga);
            cpasync16(base + ASZ + so, Alo + ga);
        }
        // B hi/lo: 256 rows x 32 cols -> 1024 chunks each
#pragma unroll
        for (int c = tid; c < 1024; c += 256) {
            int row = c >> 2, ch = (c & 3) * 8;
            size_t gb = (size_t)(n0 + row) * K + k0 + ch;
            int so = row * GST + ch;
            cpasync16(base + 2 * ASZ + so,       Bhi + gb);
            cpasync16(base + 2 * ASZ + BSZ + so, Blo + gb);
        }
    };

    int T = K / 32;
    stage_load(0, 0);
    asm volatile("cp.async.commit_group;" ::: "memory");
    stage_load(32, 1);
    asm volatile("cp.async.commit_group;" ::: "memory");

    for (int it = 0; it < T; it++) {
        asm volatile("cp.async.wait_group 1;" ::: "memory");
        __syncthreads();

        int st = it % 3;
        __nv_bfloat16* base = smg + st * STSZ;
        __nv_bfloat16* sAh = base;
        __nv_bfloat16* sAl = base + ASZ;
        __nv_bfloat16* sBh = base + 2 * ASZ;
        __nv_bfloat16* sBl = base + 2 * ASZ + BSZ;

#pragma unroll
        for (int ks = 0; ks < 32; ks += 16) {
            int col = ks + lc8;
            unsigned ah[4][4], al[4][4];
#pragma unroll
            for (int mi = 0; mi < 4; mi++) {
                int ar = wm * 64 + mi * 16 + l16;
                ldmx4(ah[mi], sAh + ar * GST + col);
                ldmx4(al[mi], sAl + ar * GST + col);
            }
#pragma unroll
            for (int nq = 0; nq < 4; nq++) {
                unsigned bh4[4], bl4[4];
                int br = wn * 64 + nq * 16 + l16;
                ldmx4(bh4, sBh + br * GST + col);
                ldmx4(bl4, sBl + br * GST + col);
#pragma unroll
                for (int mi = 0; mi < 4; mi++) {
                    mma16816_b2(acc[mi][2 * nq],     ah[mi], bh4[0], bh4[2]);
                    mma16816_b2(acc[mi][2 * nq],     ah[mi], bl4[0], bl4[2]);
                    mma16816_b2(acc[mi][2 * nq],     al[mi], bh4[0], bh4[2]);
                    mma16816_b2(acc[mi][2 * nq + 1], ah[mi], bh4[1], bh4[3]);
                    mma16816_b2(acc[mi][2 * nq + 1], ah[mi], bl4[1], bl4[3]);
                    mma16816_b2(acc[mi][2 * nq + 1], al[mi], bh4[1], bh4[3]);
                }
            }
        }
        __syncthreads();
        if (it + 2 < T) stage_load((it + 2) * 32, (it + 2) % 3);
        asm volatile("cp.async.commit_group;" ::: "memory");
    }

#pragma unroll
    for (int mi = 0; mi < 4; mi++) {
#pragma unroll
        for (int ni = 0; ni < 8; ni++) {
            int row = m0 + wm * 64 + mi * 16 + g;
            int col = n0 + wn * 64 + ni * 8 + t2;
            *(float2*)&C[(size_t)row * N + col] =
                make_float2(acc[mi][ni][0], acc[mi][ni][1]);
            *(float2*)&C[(size_t)(row + 8) * N + col] =
                make_float2(acc[mi][ni][2], acc[mi][ni][3]);
        }
    }
}

// ---------------------------------------------------------------------------
// Tensor-core flash attention, split-bf16, Br=128, Bc=64, D=64.
// S-phase fragment loads via ldmatrix.x4 (was scalar LDS).
// ---------------------------------------------------------------------------
#define AST 72

__global__ __launch_bounds__(256) void attn_mma_kernel()
{
    extern __shared__ __nv_bfloat16 smb[];
    __nv_bfloat16* sQh = smb;
    __nv_bfloat16* sQl = smb + 128 * AST;
    __nv_bfloat16* sKh = smb + 256 * AST;
    __nv_bfloat16* sKl = smb + 320 * AST;
    __nv_bfloat16* sVh = smb + 384 * AST;
    __nv_bfloat16* sVl = smb + 448 * AST;

    int tid  = threadIdx.x;
    int lane = tid & 31;
    int wid  = tid >> 5;
    int g    = lane >> 2;
    int t2   = (lane & 3) * 2;
    int l16  = lane & 15;
    int lc8  = (lane >> 4) * 8;

    int qt = blockIdx.x, h = blockIdx.y, b = blockIdx.z;
    int kvh = h >> 2;
    int s0 = qt * 128;

    const __nv_bfloat16* Qhg = g_Qbh + ((size_t)(b * S_ + s0)) * E_ + h * D_;
    const __nv_bfloat16* Qlg = g_Qbl + ((size_t)(b * S_ + s0)) * E_ + h * D_;
    const __nv_bfloat16* Khg = g_Kbh + (size_t)b * S_ * KVW + kvh * D_;
    const __nv_bfloat16* Klg = g_Kbl + (size_t)b * S_ * KVW + kvh * D_;
    const __nv_bfloat16* Vhg = g_Vbh + (size_t)b * S_ * KVW + kvh * D_;
    const __nv_bfloat16* Vlg = g_Vbl + (size_t)b * S_ * KVW + kvh * D_;

    for (int c = tid; c < 1024; c += 256) {
        int r = c >> 3, col = (c & 7) * 8;
        *(uint4*)&sQh[r * AST + col] = *(const uint4*)&Qhg[(size_t)r * E_ + col];
        *(uint4*)&sQl[r * AST + col] = *(const uint4*)&Qlg[(size_t)r * E_ + col];
    }

    int wr = wid * 16;
    float m0r = -1e30f, m1r = -1e30f, l0r = 0.0f, l1r = 0.0f;
    float O[8][4];
#pragma unroll
    for (int nt = 0; nt < 8; nt++)
#pragma unroll
        for (int r = 0; r < 4; r++) O[nt][r] = 0.0f;

    for (int kt0 = 0; kt0 < S_ / 64; kt0++) {
        int t0 = kt0 * 64;
        for (int c = tid; c < 512; c += 256) {
            int r = c >> 3, col = (c & 7) * 8;
            size_t ga = (size_t)(t0 + r) * KVW + col;
            *(uint4*)&sKh[r * AST + col] = *(const uint4*)&Khg[ga];
            *(uint4*)&sKl[r * AST + col] = *(const uint4*)&Klg[ga];
            *(uint4*)&sVh[r * AST + col] = *(const uint4*)&Vhg[ga];
            *(uint4*)&sVl[r * AST + col] = *(const uint4*)&Vlg[ga];
        }
        __syncthreads();

        float acc[8][4];
#pragma unroll
        for (int nt = 0; nt < 8; nt++)
#pragma unroll
            for (int r = 0; r < 4; r++) acc[nt][r] = 0.0f;

#pragma unroll
        for (int kt = 0; kt < 4; kt++) {
            int col = kt * 16 + lc8;
            unsigned ah[4], al[4];
            ldmx4(ah, sQh + (wr + l16) * AST + col);
            ldmx4(al, sQl + (wr + l16) * AST + col);
#pragma unroll
            for (int nq = 0; nq < 4; nq++) {
                unsigned bh4[4], bl4[4];
                ldmx4(bh4, sKh + (nq * 16 + l16) * AST + col);
                ldmx4(bl4, sKl + (nq * 16 + l16) * AST + col);
                mma16816_b2(acc[2 * nq],     ah, bh4[0], bh4[2]);
                mma16816_b2(acc[2 * nq],     ah, bl4[0], bl4[2]);
                mma16816_b2(acc[2 * nq],     al, bh4[0], bh4[2]);
                mma16816_b2(acc[2 * nq + 1], ah, bh4[1], bh4[3]);
                mma16816_b2(acc[2 * nq + 1], ah, bl4[1], bl4[3]);
                mma16816_b2(acc[2 * nq + 1], al, bh4[1], bh4[3]);
            }
        }

        float mx0 = -1e30f, mx1 = -1e30f;
#pragma unroll
        for (int nt = 0; nt < 8; nt++) {
            mx0 = fmaxf(mx0, fmaxf(acc[nt][0], acc[nt][1]));
            mx1 = fmaxf(mx1, fmaxf(acc[nt][2], acc[nt][3]));
        }
        mx0 = fmaxf(mx0, __shfl_xor_sync(0xffffffffu, mx0, 1));
        mx0 = fmaxf(mx0, __shfl_xor_sync(0xffffffffu, mx0, 2));
        mx1 = fmaxf(mx1, __shfl_xor_sync(0xffffffffu, mx1, 1));
        mx1 = fmaxf(mx1, __shfl_xor_sync(0xffffffffu, mx1, 2));
        float nm0 = fmaxf(m0r, mx0), nm1 = fmaxf(m1r, mx1);
        float corr0 = __expf(m0r - nm0), corr1 = __expf(m1r - nm1);
        m0r = nm0; m1r = nm1;

        float sum0 = 0.0f, sum1 = 0.0f;
#pragma unroll
        for (int nt = 0; nt < 8; nt++) {
            acc[nt][0] = __expf(acc[nt][0] - nm0); sum0 += acc[nt][0];
            acc[nt][1] = __expf(acc[nt][1] - nm0); sum0 += acc[nt][1];
            acc[nt][2] = __expf(acc[nt][2] - nm1); sum1 += acc[nt][2];
            acc[nt][3] = __expf(acc[nt][3] - nm1); sum1 += acc[nt][3];
        }
        sum0 += __shfl_xor_sync(0xffffffffu, sum0, 1);
        sum0 += __shfl_xor_sync(0xffffffffu, sum0, 2);
        sum1 += __shfl_xor_sync(0xffffffffu, sum1, 1);
        sum1 += __shfl_xor_sync(0xffffffffu, sum1, 2);
        l0r = l0r * corr0 + sum0;
        l1r = l1r * corr1 + sum1;
#pragma unroll
        for (int nt = 0; nt < 8; nt++) {
            O[nt][0] *= corr0; O[nt][1] *= corr0;
            O[nt][2] *= corr1; O[nt][3] *= corr1;
        }

#pragma unroll
        for (int kt = 0; kt < 4; kt++) {
            unsigned ph[4], pl[4];
            split2(acc[2 * kt][0],     acc[2 * kt][1],     ph[0], pl[0]);
            split2(acc[2 * kt][2],     acc[2 * kt][3],     ph[1], pl[1]);
            split2(acc[2 * kt + 1][0], acc[2 * kt + 1][1], ph[2], pl[2]);
            split2(acc[2 * kt + 1][2], acc[2 * kt + 1][3], ph[3], pl[3]);
            const __nv_bfloat16* vh_base = sVh + (kt * 16 + l16) * AST;
            const __nv_bfloat16* vl_base = sVl + (kt * 16 + l16) * AST;
#pragma unroll
            for (int nt = 0; nt < 8; nt++) {
                unsigned bh[2], bl[2];
                ldmx2t(bh[0], bh[1], vh_base + nt * 8);
                ldmx2t(bl[0], bl[1], vl_base + nt * 8);
                mma16816(O[nt], ph, bh);
                mma16816(O[nt], ph, bl);
                mma16816(O[nt], pl, bh);
            }
        }
        __syncthreads();
    }

    float inv0 = 1.0f / l0r, inv1 = 1.0f / l1r;
    size_t row0 = (size_t)(b * S_ + s0 + wr + g) * E_ + h * D_;
    size_t row1 = (size_t)(b * S_ + s0 + wr + g + 8) * E_ + h * D_;
#pragma unroll
    for (int nt = 0; nt < 8; nt++) {
        unsigned hi, lo;
        split2(O[nt][0] * inv0, O[nt][1] * inv0, hi, lo);
        *(unsigned*)&g_attn_hi[row0 + nt * 8 + t2] = hi;
        *(unsigned*)&g_attn_lo[row0 + nt * 8 + t2] = lo;
        split2(O[nt][2] * inv1, O[nt][3] * inv1, hi, lo);
        *(unsigned*)&g_attn_hi[row1 + nt * 8 + t2] = hi;
        *(unsigned*)&g_attn_lo[row1 + nt * 8 + t2] = lo;
    }
}

// ---------------------------------------------------------------------------
// Launch
// ---------------------------------------------------------------------------
extern "C" void kernel_launch(void* const* d_in, const int* in_sizes, int n_in,
                              void* d_out, int out_size)
{
    const float* x    = (const float*)d_in[0];
    const float* cosT = (const float*)d_in[1];
    const float* sinT = (const float*)d_in[2];
    const float* Wq   = (const float*)d_in[3];
    const float* Wk   = (const float*)d_in[4];
    const float* Wv   = (const float*)d_in[5];
    const float* Wo   = (const float*)d_in[6];
    float* out = (float*)d_out;

    float* QKVp;
    __nv_bfloat16 *xh, *xl, *wh, *wl, *oh, *ol;
    __nv_bfloat16 *qbh, *qbl, *kbh, *kbl, *vbh, *vbl, *ah, *al;
    cudaGetSymbolAddress((void**)&QKVp, g_QKV);
    cudaGetSymbolAddress((void**)&xh, g_x_hi);    cudaGetSymbolAddress((void**)&xl, g_x_lo);
    cudaGetSymbolAddress((void**)&wh, g_Wqkv_hi); cudaGetSymbolAddress((void**)&wl, g_Wqkv_lo);
    cudaGetSymbolAddress((void**)&oh, g_Wo_hi);   cudaGetSymbolAddress((void**)&ol, g_Wo_lo);
    cudaGetSymbolAddress((void**)&qbh, g_Qbh);    cudaGetSymbolAddress((void**)&qbl, g_Qbl);
    cudaGetSymbolAddress((void**)&kbh, g_Kbh);    cudaGetSymbolAddress((void**)&kbl, g_Kbl);
    cudaGetSymbolAddress((void**)&vbh, g_Vbh);    cudaGetSymbolAddress((void**)&vbl, g_Vbl);
    cudaGetSymbolAddress((void**)&ah, g_attn_hi); cudaGetSymbolAddress((void**)&al, g_attn_lo);

    const int M = B_ * S_;   // 4096

    cudaFuncSetAttribute(gemm_split_nt3_kernel,
                         cudaFuncAttributeMaxDynamicSharedMemorySize, GEMM_SMEM);
    cudaFuncSetAttribute(attn_mma_kernel,
                         cudaFuncAttributeMaxDynamicSharedMemorySize,
                         512 * AST * (int)sizeof(__nv_bfloat16));

    // Split conversions: x, and weights into fused [Wq;Wk;Wv] buffer
    {
        int nx = M * E_;
        split_kernel<<<(nx + 255) / 256, 256>>>(x, xh, xl, nx);
        int nq = E_ * E_;
        int nk = KVW * E_;
        split_kernel<<<(nq + 255) / 256, 256>>>(Wq, wh, wl, nq);
        split_kernel<<<(nk + 255) / 256, 256>>>(Wk, wh + (size_t)E_ * E_,
                                                wl + (size_t)E_ * E_, nk);
        split_kernel<<<(nk + 255) / 256, 256>>>(Wv, wh + (size_t)(E_ + KVW) * E_,
                                                wl + (size_t)(E_ + KVW) * E_, nk);
        split_kernel<<<(nq + 255) / 256, 256>>>(Wo, oh, ol, nq);
    }

    // Fused QKV projection: [4096, 3072]
    gemm_split_nt3_kernel<<<dim3(NQKV / 256, M / 128), 256, GEMM_SMEM>>>(
        xh, xl, wh, wl, QKVp, M, NQKV, E_);

    // RoPE + scale + split (strided reads from fused QKV); V strided split
    {
        int totQ = B_ * S_ * H_ * (D_ / 2);
        rope_split_kernel<<<(totQ + 255) / 256, 256>>>(QKVp, NQKV, cosT, sinT,
                                                       H_, 0.125f, qbh, qbl);
        int totK = B_ * S_ * HKV_ * (D_ / 2);
        rope_split_kernel<<<(totK + 255) / 256, 256>>>(QKVp + E_, NQKV, cosT, sinT,
                                                       HKV_, 1.0f, kbh, kbl);
        int nv = M * KVW;
        split_strided_kernel<<<(nv + 255) / 256, 256>>>(QKVp + E_ + KVW, NQKV,
                                                        M, KVW, vbh, vbl);
    }

    // Attention
    attn_mma_kernel<<<dim3(S_ / 128, H_, B_), 256,
                      512 * AST * sizeof(__nv_bfloat16)>>>();

    // Output projection -> d_out
    gemm_split_nt3_kernel<<<dim3(E_ / 256, M / 128), 256, GEMM_SMEM>>>(
        ah, al, oh, ol, out, M, E_, E_);
}